// round 1
// baseline (speedup 1.0000x reference)
#include <cuda_runtime.h>
#include <cuda_bf16.h>
#include <math.h>

// Problem constants
#define B_  2
#define S_  2048
#define D_  2048
#define H_  16
#define HD_ 128
#define M_  (B_*S_)           // 4096 rows for projection GEMMs

// Scratch buffers (allocation-free rule: __device__ globals)
__device__ float g_q[M_*D_];
__device__ float g_k[M_*D_];
__device__ float g_v[M_*D_];
__device__ float g_a[M_*D_];

// ---------------------------------------------------------------------------
// NT GEMM: C[m,n] = sum_k A[m,k] * W[n,k],  N = K = 2048 fixed, M via gridDim.y
// Tile 128x128x8, 256 threads, 8x8 per thread.
// ---------------------------------------------------------------------------
__global__ __launch_bounds__(256) void gemm_nt_kernel(
    const float* __restrict__ A, const float* __restrict__ W,
    float* __restrict__ C) {
    const int K = D_;
    __shared__ float As[8][128];
    __shared__ float Bs[8][128];

    const int tid = threadIdx.x;
    const int tx  = tid & 15;          // 0..15 -> N
    const int ty  = tid >> 4;          // 0..15 -> M
    const int mBase = blockIdx.y << 7;
    const int nBase = blockIdx.x << 7;

    float acc[8][8];
#pragma unroll
    for (int i = 0; i < 8; i++)
#pragma unroll
        for (int j = 0; j < 8; j++) acc[i][j] = 0.0f;

    const int lrow = tid >> 1;         // 0..127
    const int lk   = (tid & 1) << 2;   // 0 or 4
    const float* Ap = A + (size_t)(mBase + lrow) * K + lk;
    const float* Wp = W + (size_t)(nBase + lrow) * K + lk;

    for (int k0 = 0; k0 < K; k0 += 8) {
        float4 av = *(const float4*)(Ap + k0);
        float4 wv = *(const float4*)(Wp + k0);
        As[lk+0][lrow] = av.x; As[lk+1][lrow] = av.y;
        As[lk+2][lrow] = av.z; As[lk+3][lrow] = av.w;
        Bs[lk+0][lrow] = wv.x; Bs[lk+1][lrow] = wv.y;
        Bs[lk+2][lrow] = wv.z; Bs[lk+3][lrow] = wv.w;
        __syncthreads();

#pragma unroll
        for (int kk = 0; kk < 8; kk++) {
            float a[8], b[8];
            *(float4*)&a[0] = *(const float4*)&As[kk][ty << 3];
            *(float4*)&a[4] = *(const float4*)&As[kk][(ty << 3) + 4];
            *(float4*)&b[0] = *(const float4*)&Bs[kk][tx << 3];
            *(float4*)&b[4] = *(const float4*)&Bs[kk][(tx << 3) + 4];
#pragma unroll
            for (int i = 0; i < 8; i++)
#pragma unroll
                for (int j = 0; j < 8; j++)
                    acc[i][j] += a[i] * b[j];
        }
        __syncthreads();
    }

#pragma unroll
    for (int i = 0; i < 8; i++) {
        float* cp = C + (size_t)(mBase + (ty << 3) + i) * D_ + nBase + (tx << 3);
        *(float4*)cp       = make_float4(acc[i][0], acc[i][1], acc[i][2], acc[i][3]);
        *(float4*)(cp + 4) = make_float4(acc[i][4], acc[i][5], acc[i][6], acc[i][7]);
    }
}

// ---------------------------------------------------------------------------
// RoPE applied in-place to Q and K. One thread per (b,s,h,pair).
// ---------------------------------------------------------------------------
__global__ void rope_kernel(float* __restrict__ Q, float* __restrict__ Kt,
                            const float* __restrict__ cosF,
                            const float* __restrict__ sinF) {
    int idx = blockIdx.x * blockDim.x + threadIdx.x;   // B*S*H*64 total
    if (idx >= B_ * S_ * H_ * (HD_ / 2)) return;
    int i = idx & 63;
    int h = (idx >> 6) & (H_ - 1);
    int s = (idx >> 10) & (S_ - 1);
    int b = idx >> 21;
    size_t base = ((size_t)(b * S_ + s)) * D_ + h * HD_ + 2 * i;
    float c  = cosF[s * 64 + i];
    float sn = sinF[s * 64 + i];
    float qr = Q[base], qi = Q[base + 1];
    Q[base]     = qr * c - qi * sn;
    Q[base + 1] = qr * sn + qi * c;
    float kr = Kt[base], ki = Kt[base + 1];
    Kt[base]     = kr * c - ki * sn;
    Kt[base + 1] = kr * sn + ki * c;
}

// ---------------------------------------------------------------------------
// Causal flash attention. One block per (q-tile of 64, head, batch).
// smem: Qs/Ks/Vs 64x129 (pad -> conflict-free), Ps 64x65.
// Thread (ty,tx): rows ty*4+rr, score cols tx+16*cc, out cols tx+16*jj.
// ---------------------------------------------------------------------------
__global__ __launch_bounds__(256) void flash_kernel(
    const float* __restrict__ Q, const float* __restrict__ Kg,
    const float* __restrict__ Vg, float* __restrict__ Og) {
    extern __shared__ float sm[];
    float* Qs = sm;                    // 64*129
    float* Ks = Qs + 64 * 129;
    float* Vs = Ks + 64 * 129;
    float* Ps = Vs + 64 * 129;         // 64*65

    const int qt = blockIdx.x;
    const int h  = blockIdx.y;
    const int b  = blockIdx.z;
    const int tid = threadIdx.x;
    const int tx = tid & 15;
    const int ty = tid >> 4;
    const float scale = 0.08838834764831845f;   // 1/sqrt(128)

    const size_t bh = ((size_t)b * S_) * D_ + (size_t)h * HD_;
    const int q0 = qt * 64;

    // Load Q tile
    {
        const float* src = Q + bh + (size_t)q0 * D_;
        for (int i = tid; i < 64 * 32; i += 256) {
            int r = i >> 5, c = (i & 31) << 2;
            float4 v = *(const float4*)&src[(size_t)r * D_ + c];
            float* d = &Qs[r * 129 + c];
            d[0] = v.x; d[1] = v.y; d[2] = v.z; d[3] = v.w;
        }
    }

    float acc[4][8];
#pragma unroll
    for (int rr = 0; rr < 4; rr++)
#pragma unroll
        for (int jj = 0; jj < 8; jj++) acc[rr][jj] = 0.0f;
    float mrun[4] = {-1e30f, -1e30f, -1e30f, -1e30f};
    float lrun[4] = {0.f, 0.f, 0.f, 0.f};

    for (int kt = 0; kt <= qt; kt++) {
        __syncthreads();   // previous PV done before overwriting Ks/Vs
        {
            const float* ks = Kg + bh + (size_t)(kt * 64) * D_;
            const float* vsrc = Vg + bh + (size_t)(kt * 64) * D_;
            for (int i = tid; i < 64 * 32; i += 256) {
                int r = i >> 5, c = (i & 31) << 2;
                float4 v1 = *(const float4*)&ks[(size_t)r * D_ + c];
                float* d1 = &Ks[r * 129 + c];
                d1[0] = v1.x; d1[1] = v1.y; d1[2] = v1.z; d1[3] = v1.w;
                float4 v2 = *(const float4*)&vsrc[(size_t)r * D_ + c];
                float* d2 = &Vs[r * 129 + c];
                d2[0] = v2.x; d2[1] = v2.y; d2[2] = v2.z; d2[3] = v2.w;
            }
        }
        __syncthreads();

        // Scores: s[rr][cc] = Q[row] . K[col]
        float sv[4][4];
#pragma unroll
        for (int rr = 0; rr < 4; rr++)
#pragma unroll
            for (int cc = 0; cc < 4; cc++) sv[rr][cc] = 0.0f;

#pragma unroll 8
        for (int d = 0; d < 128; d++) {
            float qv[4], kv[4];
#pragma unroll
            for (int rr = 0; rr < 4; rr++) qv[rr] = Qs[(ty * 4 + rr) * 129 + d];
#pragma unroll
            for (int cc = 0; cc < 4; cc++) kv[cc] = Ks[(tx + 16 * cc) * 129 + d];
#pragma unroll
            for (int rr = 0; rr < 4; rr++)
#pragma unroll
                for (int cc = 0; cc < 4; cc++)
                    sv[rr][cc] += qv[rr] * kv[cc];
        }

        const bool diag = (kt == qt);
#pragma unroll
        for (int rr = 0; rr < 4; rr++) {
            const int qi = q0 + ty * 4 + rr;
            float mloc = -1e30f;
#pragma unroll
            for (int cc = 0; cc < 4; cc++) {
                int ki = kt * 64 + tx + 16 * cc;
                float s = (diag && ki > qi) ? -1e30f : sv[rr][cc] * scale;
                sv[rr][cc] = s;
                mloc = fmaxf(mloc, s);
            }
#pragma unroll
            for (int off = 8; off >= 1; off >>= 1)
                mloc = fmaxf(mloc, __shfl_xor_sync(0xffffffffu, mloc, off));
            float mnew = fmaxf(mrun[rr], mloc);
            float al = __expf(mrun[rr] - mnew);
            float ls = 0.0f;
#pragma unroll
            for (int cc = 0; cc < 4; cc++) {
                float p = __expf(sv[rr][cc] - mnew);
                sv[rr][cc] = p;
                ls += p;
            }
#pragma unroll
            for (int off = 8; off >= 1; off >>= 1)
                ls += __shfl_xor_sync(0xffffffffu, ls, off);
            lrun[rr] = lrun[rr] * al + ls;
            mrun[rr] = mnew;
#pragma unroll
            for (int jj = 0; jj < 8; jj++) acc[rr][jj] *= al;
#pragma unroll
            for (int cc = 0; cc < 4; cc++)
                Ps[(ty * 4 + rr) * 65 + tx + 16 * cc] = sv[rr][cc];
        }
        __syncthreads();

        // PV: acc[rr][jj] += sum_c P[row][c] * V[c][col]
#pragma unroll 4
        for (int c = 0; c < 64; c++) {
            float vv[8];
#pragma unroll
            for (int jj = 0; jj < 8; jj++) vv[jj] = Vs[c * 129 + tx + 16 * jj];
#pragma unroll
            for (int rr = 0; rr < 4; rr++) {
                float p = Ps[(ty * 4 + rr) * 65 + c];
#pragma unroll
                for (int jj = 0; jj < 8; jj++) acc[rr][jj] += p * vv[jj];
            }
        }
    }

    // Epilogue: normalize and store to g_a laid out as [B,S,H,HD]
#pragma unroll
    for (int rr = 0; rr < 4; rr++) {
        float inv = 1.0f / lrun[rr];
        int row = q0 + ty * 4 + rr;
#pragma unroll
        for (int jj = 0; jj < 8; jj++)
            Og[bh + (size_t)row * D_ + tx + 16 * jj] = acc[rr][jj] * inv;
    }
}

// ---------------------------------------------------------------------------
extern "C" void kernel_launch(void* const* d_in, const int* in_sizes, int n_in,
                              void* d_out, int out_size) {
    const float* x  = (const float*)d_in[0];
    const float* wq = (const float*)d_in[1];
    const float* wk = (const float*)d_in[2];
    const float* wv = (const float*)d_in[3];
    const float* wo = (const float*)d_in[4];
    const float* fc = (const float*)d_in[5];
    const float* fs = (const float*)d_in[6];
    // d_in[7] = mask (causal triu NEG, applied analytically), d_in[8] = start_pos (0)
    float* out = (float*)d_out;

    void *pq, *pk, *pv, *pa;
    cudaGetSymbolAddress(&pq, g_q);
    cudaGetSymbolAddress(&pk, g_k);
    cudaGetSymbolAddress(&pv, g_v);
    cudaGetSymbolAddress(&pa, g_a);

    const int FLASH_SMEM = (3 * 64 * 129 + 64 * 65) * 4;   // 115,712 B
    cudaFuncSetAttribute(flash_kernel,
                         cudaFuncAttributeMaxDynamicSharedMemorySize, FLASH_SMEM);

    dim3 gemmGrid(D_ / 128, M_ / 128);   // (16, 32)

    gemm_nt_kernel<<<gemmGrid, 256>>>(x, wq, (float*)pq);
    gemm_nt_kernel<<<gemmGrid, 256>>>(x, wk, (float*)pk);
    gemm_nt_kernel<<<gemmGrid, 256>>>(x, wv, (float*)pv);

    int ropeN = B_ * S_ * H_ * (HD_ / 2);
    rope_kernel<<<(ropeN + 255) / 256, 256>>>((float*)pq, (float*)pk, fc, fs);

    flash_kernel<<<dim3(S_ / 64, H_, B_), 256, FLASH_SMEM>>>(
        (const float*)pq, (const float*)pk, (const float*)pv, (float*)pa);

    gemm_nt_kernel<<<gemmGrid, 256>>>((const float*)pa, wo, out);
}

// round 3
// speedup vs baseline: 1.6795x; 1.6795x over previous
#include <cuda_runtime.h>
#include <cuda_bf16.h>
#include <math.h>
#include <stdint.h>

// Problem constants
#define B_  2
#define S_  2048
#define D_  2048
#define H_  16
#define HD_ 128
#define M_  (B_*S_)           // 4096 rows for projection GEMMs

// Scratch buffers (allocation-free rule: __device__ globals)
__device__ float g_q[M_*D_];
__device__ float g_k[M_*D_];
__device__ float g_v[M_*D_];
__device__ float g_a[M_*D_];

__device__ __forceinline__ uint32_t f2tf(float f) {
    uint32_t r;
    asm("cvt.rna.tf32.f32 %0, %1;" : "=r"(r) : "f"(f));
    return r;
}

// mma.sync m16n8k8 tf32 (baseline PTX ISA, works on compute_103 non-'a')
__device__ __forceinline__ void mma1688(float* d, const uint32_t* a, const uint32_t* b) {
    asm volatile(
        "mma.sync.aligned.m16n8k8.row.col.f32.tf32.tf32.f32 "
        "{%0,%1,%2,%3}, {%4,%5,%6,%7}, {%8,%9}, {%0,%1,%2,%3};"
        : "+f"(d[0]), "+f"(d[1]), "+f"(d[2]), "+f"(d[3])
        : "r"(a[0]), "r"(a[1]), "r"(a[2]), "r"(a[3]), "r"(b[0]), "r"(b[1]));
}

// ============================================================================
// tf32 warp-MMA GEMM:  C[m,n] = sum_k A[m,k] * W[n,k]   (NT, K = D_ = 2048)
// CTA tile 128x128, K-chunk 32, 8 warps of 64x32, double-buffered smem.
// Smem row stride 36 floats -> conflict-free fragment LDS.
// ============================================================================
#define KCH   32
#define SSTR  36
#define STAGE_FLOATS (128 * SSTR)              // 4608
#define GEMM_SMEM_BYTES (4 * STAGE_FLOATS * 4) // As0,As1,Bs0,Bs1 = 73728 B

__global__ __launch_bounds__(256, 1) void gemm_mma_kernel(
    const float* __restrict__ A, const float* __restrict__ W,
    float* __restrict__ C) {
    extern __shared__ float smg[];
    float* Asm[2] = { smg,                  smg + STAGE_FLOATS };
    float* Bsm[2] = { smg + 2*STAGE_FLOATS, smg + 3*STAGE_FLOATS };

    const int tid  = threadIdx.x;
    const int wid  = tid >> 5;
    const int lane = tid & 31;
    const int lr   = lane >> 2;    // 0..7
    const int lc   = lane & 3;     // 0..3
    const int wm   = wid & 1;      // 2 warps over M
    const int wn   = wid >> 1;     // 4 warps over N
    const int mBase = blockIdx.y << 7;
    const int nBase = blockIdx.x << 7;

    // Global-load staging: 4 float4 for A + 4 for B per thread per stage.
    // fidx = p*256 + tid ; row = fidx>>3 (0..127), c4 = fidx&7 (k-quads)
    const int grow = tid >> 3;      // base row for p=0 (rows advance by 32/pass)
    const int gc4  = tid & 7;
    const float* Ag = A + (size_t)(mBase + grow) * D_ + gc4 * 4;
    const float* Wg = W + (size_t)(nBase + grow) * D_ + gc4 * 4;

    float4 ra[4], rb[4];
#define GLOAD(k0)                                                        \
    {                                                                    \
        _Pragma("unroll")                                                \
        for (int p = 0; p < 4; ++p) {                                    \
            ra[p] = *(const float4*)(Ag + (size_t)(p*32) * D_ + (k0));   \
            rb[p] = *(const float4*)(Wg + (size_t)(p*32) * D_ + (k0));   \
        }                                                                \
    }
#define SSTORE(buf)                                                      \
    {                                                                    \
        _Pragma("unroll")                                                \
        for (int p = 0; p < 4; ++p) {                                    \
            float* da = &Asm[buf][(grow + p*32) * SSTR + gc4 * 4];       \
            da[0] = __uint_as_float(f2tf(ra[p].x));                      \
            da[1] = __uint_as_float(f2tf(ra[p].y));                      \
            da[2] = __uint_as_float(f2tf(ra[p].z));                      \
            da[3] = __uint_as_float(f2tf(ra[p].w));                      \
            float* db = &Bsm[buf][(grow + p*32) * SSTR + gc4 * 4];       \
            db[0] = __uint_as_float(f2tf(rb[p].x));                      \
            db[1] = __uint_as_float(f2tf(rb[p].y));                      \
            db[2] = __uint_as_float(f2tf(rb[p].z));                      \
            db[3] = __uint_as_float(f2tf(rb[p].w));                      \
        }                                                                \
    }

    float acc[4][4][4];
#pragma unroll
    for (int mf = 0; mf < 4; ++mf)
#pragma unroll
        for (int nf = 0; nf < 4; ++nf)
#pragma unroll
            for (int q = 0; q < 4; ++q) acc[mf][nf][q] = 0.0f;

    const int NS = D_ / KCH;   // 64 stages

    // Prologue: stage 0 into smem buf0; stage 1 into regs.
    GLOAD(0);
    SSTORE(0);
    GLOAD(KCH);
    __syncthreads();

    for (int s = 0; s < NS; ++s) {
        const int b = s & 1;
        const float* As = Asm[b];
        const float* Bs = Bsm[b];

#pragma unroll
        for (int ks = 0; ks < 4; ++ks) {
            const int k0 = ks * 8;
            uint32_t af[4][4];
#pragma unroll
            for (int mf = 0; mf < 4; ++mf) {
                const float* ap = &As[(wm*64 + mf*16 + lr) * SSTR + k0 + lc];
                af[mf][0] = __float_as_uint(ap[0]);
                af[mf][1] = __float_as_uint(ap[8 * SSTR]);
                af[mf][2] = __float_as_uint(ap[4]);
                af[mf][3] = __float_as_uint(ap[8 * SSTR + 4]);
            }
            uint32_t bf[4][2];
#pragma unroll
            for (int nf = 0; nf < 4; ++nf) {
                const float* bp = &Bs[(wn*32 + nf*8 + lr) * SSTR + k0 + lc];
                bf[nf][0] = __float_as_uint(bp[0]);
                bf[nf][1] = __float_as_uint(bp[4]);
            }
#pragma unroll
            for (int mf = 0; mf < 4; ++mf)
#pragma unroll
                for (int nf = 0; nf < 4; ++nf)
                    mma1688(acc[mf][nf], af[mf], bf[nf]);
        }

        if (s + 1 < NS) {
            SSTORE(1 - b);                 // buf (1-b) last read at stage s-1
            if (s + 2 < NS) GLOAD((s + 2) * KCH);
        }
        __syncthreads();
    }

    // Epilogue: acc -> C.  c0,c1 at (row, 2lc); c2,c3 at (row+8, 2lc).
#pragma unroll
    for (int mf = 0; mf < 4; ++mf) {
#pragma unroll
        for (int nf = 0; nf < 4; ++nf) {
            const int row = mBase + wm*64 + mf*16 + lr;
            const int col = nBase + wn*32 + nf*8 + 2*lc;
            *(float2*)&C[(size_t)row * D_ + col] =
                make_float2(acc[mf][nf][0], acc[mf][nf][1]);
            *(float2*)&C[(size_t)(row + 8) * D_ + col] =
                make_float2(acc[mf][nf][2], acc[mf][nf][3]);
        }
    }
#undef GLOAD
#undef SSTORE
}

// ---------------------------------------------------------------------------
// RoPE applied in-place to Q and K. One thread per (b,s,h,pair).
// ---------------------------------------------------------------------------
__global__ void rope_kernel(float* __restrict__ Q, float* __restrict__ Kt,
                            const float* __restrict__ cosF,
                            const float* __restrict__ sinF) {
    int idx = blockIdx.x * blockDim.x + threadIdx.x;   // B*S*H*64 total
    if (idx >= B_ * S_ * H_ * (HD_ / 2)) return;
    int i = idx & 63;
    int h = (idx >> 6) & (H_ - 1);
    int s = (idx >> 10) & (S_ - 1);
    int b = idx >> 21;
    size_t base = ((size_t)(b * S_ + s)) * D_ + h * HD_ + 2 * i;
    float c  = cosF[s * 64 + i];
    float sn = sinF[s * 64 + i];
    float qr = Q[base], qi = Q[base + 1];
    Q[base]     = qr * c - qi * sn;
    Q[base + 1] = qr * sn + qi * c;
    float kr = Kt[base], ki = Kt[base + 1];
    Kt[base]     = kr * c - ki * sn;
    Kt[base + 1] = kr * sn + ki * c;
}

// ---------------------------------------------------------------------------
// Causal flash attention (SIMT fp32). One block per (q-tile of 64, head, batch).
// ---------------------------------------------------------------------------
__global__ __launch_bounds__(256) void flash_kernel(
    const float* __restrict__ Q, const float* __restrict__ Kg,
    const float* __restrict__ Vg, float* __restrict__ Og) {
    extern __shared__ float smf[];
    float* Qs = smf;                   // 64*129
    float* Ks = Qs + 64 * 129;
    float* Vs = Ks + 64 * 129;
    float* Ps = Vs + 64 * 129;         // 64*65

    const int qt = blockIdx.x;
    const int h  = blockIdx.y;
    const int b  = blockIdx.z;
    const int tid = threadIdx.x;
    const int tx = tid & 15;
    const int ty = tid >> 4;
    const float scale = 0.08838834764831845f;   // 1/sqrt(128)

    const size_t bh = ((size_t)b * S_) * D_ + (size_t)h * HD_;
    const int q0 = qt * 64;

    {
        const float* src = Q + bh + (size_t)q0 * D_;
        for (int i = tid; i < 64 * 32; i += 256) {
            int r = i >> 5, c = (i & 31) << 2;
            float4 v = *(const float4*)&src[(size_t)r * D_ + c];
            float* d = &Qs[r * 129 + c];
            d[0] = v.x; d[1] = v.y; d[2] = v.z; d[3] = v.w;
        }
    }

    float acc[4][8];
#pragma unroll
    for (int rr = 0; rr < 4; rr++)
#pragma unroll
        for (int jj = 0; jj < 8; jj++) acc[rr][jj] = 0.0f;
    float mrun[4] = {-1e30f, -1e30f, -1e30f, -1e30f};
    float lrun[4] = {0.f, 0.f, 0.f, 0.f};

    for (int kt = 0; kt <= qt; kt++) {
        __syncthreads();
        {
            const float* ks = Kg + bh + (size_t)(kt * 64) * D_;
            const float* vsrc = Vg + bh + (size_t)(kt * 64) * D_;
            for (int i = tid; i < 64 * 32; i += 256) {
                int r = i >> 5, c = (i & 31) << 2;
                float4 v1 = *(const float4*)&ks[(size_t)r * D_ + c];
                float* d1 = &Ks[r * 129 + c];
                d1[0] = v1.x; d1[1] = v1.y; d1[2] = v1.z; d1[3] = v1.w;
                float4 v2 = *(const float4*)&vsrc[(size_t)r * D_ + c];
                float* d2 = &Vs[r * 129 + c];
                d2[0] = v2.x; d2[1] = v2.y; d2[2] = v2.z; d2[3] = v2.w;
            }
        }
        __syncthreads();

        float sv[4][4];
#pragma unroll
        for (int rr = 0; rr < 4; rr++)
#pragma unroll
            for (int cc = 0; cc < 4; cc++) sv[rr][cc] = 0.0f;

#pragma unroll 8
        for (int d = 0; d < 128; d++) {
            float qv[4], kv[4];
#pragma unroll
            for (int rr = 0; rr < 4; rr++) qv[rr] = Qs[(ty * 4 + rr) * 129 + d];
#pragma unroll
            for (int cc = 0; cc < 4; cc++) kv[cc] = Ks[(tx + 16 * cc) * 129 + d];
#pragma unroll
            for (int rr = 0; rr < 4; rr++)
#pragma unroll
                for (int cc = 0; cc < 4; cc++)
                    sv[rr][cc] += qv[rr] * kv[cc];
        }

        const bool diag = (kt == qt);
#pragma unroll
        for (int rr = 0; rr < 4; rr++) {
            const int qi = q0 + ty * 4 + rr;
            float mloc = -1e30f;
#pragma unroll
            for (int cc = 0; cc < 4; cc++) {
                int ki = kt * 64 + tx + 16 * cc;
                float s = (diag && ki > qi) ? -1e30f : sv[rr][cc] * scale;
                sv[rr][cc] = s;
                mloc = fmaxf(mloc, s);
            }
#pragma unroll
            for (int off = 8; off >= 1; off >>= 1)
                mloc = fmaxf(mloc, __shfl_xor_sync(0xffffffffu, mloc, off));
            float mnew = fmaxf(mrun[rr], mloc);
            float al = __expf(mrun[rr] - mnew);
            float ls = 0.0f;
#pragma unroll
            for (int cc = 0; cc < 4; cc++) {
                float p = __expf(sv[rr][cc] - mnew);
                sv[rr][cc] = p;
                ls += p;
            }
#pragma unroll
            for (int off = 8; off >= 1; off >>= 1)
                ls += __shfl_xor_sync(0xffffffffu, ls, off);
            lrun[rr] = lrun[rr] * al + ls;
            mrun[rr] = mnew;
#pragma unroll
            for (int jj = 0; jj < 8; jj++) acc[rr][jj] *= al;
#pragma unroll
            for (int cc = 0; cc < 4; cc++)
                Ps[(ty * 4 + rr) * 65 + tx + 16 * cc] = sv[rr][cc];
        }
        __syncthreads();

#pragma unroll 4
        for (int c = 0; c < 64; c++) {
            float vv[8];
#pragma unroll
            for (int jj = 0; jj < 8; jj++) vv[jj] = Vs[c * 129 + tx + 16 * jj];
#pragma unroll
            for (int rr = 0; rr < 4; rr++) {
                float p = Ps[(ty * 4 + rr) * 65 + c];
#pragma unroll
                for (int jj = 0; jj < 8; jj++) acc[rr][jj] += p * vv[jj];
            }
        }
    }

#pragma unroll
    for (int rr = 0; rr < 4; rr++) {
        float inv = 1.0f / lrun[rr];
        int row = q0 + ty * 4 + rr;
#pragma unroll
        for (int jj = 0; jj < 8; jj++)
            Og[bh + (size_t)row * D_ + tx + 16 * jj] = acc[rr][jj] * inv;
    }
}

// ---------------------------------------------------------------------------
extern "C" void kernel_launch(void* const* d_in, const int* in_sizes, int n_in,
                              void* d_out, int out_size) {
    const float* x  = (const float*)d_in[0];
    const float* wq = (const float*)d_in[1];
    const float* wk = (const float*)d_in[2];
    const float* wv = (const float*)d_in[3];
    const float* wo = (const float*)d_in[4];
    const float* fc = (const float*)d_in[5];
    const float* fs = (const float*)d_in[6];
    float* out = (float*)d_out;

    void *pq, *pk, *pv, *pa;
    cudaGetSymbolAddress(&pq, g_q);
    cudaGetSymbolAddress(&pk, g_k);
    cudaGetSymbolAddress(&pv, g_v);
    cudaGetSymbolAddress(&pa, g_a);

    const int FLASH_SMEM = (3 * 64 * 129 + 64 * 65) * 4;   // 115,712 B
    cudaFuncSetAttribute(flash_kernel,
                         cudaFuncAttributeMaxDynamicSharedMemorySize, FLASH_SMEM);
    cudaFuncSetAttribute(gemm_mma_kernel,
                         cudaFuncAttributeMaxDynamicSharedMemorySize, GEMM_SMEM_BYTES);

    dim3 gemmGrid(D_ / 128, M_ / 128);   // (16, 32)

    gemm_mma_kernel<<<gemmGrid, 256, GEMM_SMEM_BYTES>>>(x, wq, (float*)pq);
    gemm_mma_kernel<<<gemmGrid, 256, GEMM_SMEM_BYTES>>>(x, wk, (float*)pk);
    gemm_mma_kernel<<<gemmGrid, 256, GEMM_SMEM_BYTES>>>(x, wv, (float*)pv);

    int ropeN = B_ * S_ * H_ * (HD_ / 2);
    rope_kernel<<<(ropeN + 255) / 256, 256>>>((float*)pq, (float*)pk, fc, fs);

    flash_kernel<<<dim3(S_ / 64, H_, B_), 256, FLASH_SMEM>>>(
        (const float*)pq, (const float*)pk, (const float*)pv, (float*)pa);

    gemm_mma_kernel<<<gemmGrid, 256, GEMM_SMEM_BYTES>>>((const float*)pa, wo, out);
}

// round 4
// speedup vs baseline: 2.3666x; 1.4091x over previous
#include <cuda_runtime.h>
#include <cuda_bf16.h>
#include <math.h>
#include <stdint.h>

// Problem constants
#define B_  2
#define S_  2048
#define D_  2048
#define H_  16
#define HD_ 128
#define M_  (B_*S_)           // 4096 rows for projection GEMMs

// Scratch buffers (allocation-free rule: __device__ globals)
__device__ float g_q[M_*D_];
__device__ float g_k[M_*D_];
__device__ float g_v[M_*D_];
__device__ float g_a[M_*D_];

__device__ __forceinline__ uint32_t f2tf(float f) {
    uint32_t r;
    asm("cvt.rna.tf32.f32 %0, %1;" : "=r"(r) : "f"(f));
    return r;
}

// mma.sync m16n8k8 tf32 (baseline PTX ISA, works on compute_103 non-'a')
__device__ __forceinline__ void mma1688(float* d, const uint32_t* a,
                                        uint32_t b0, uint32_t b1) {
    asm volatile(
        "mma.sync.aligned.m16n8k8.row.col.f32.tf32.tf32.f32 "
        "{%0,%1,%2,%3}, {%4,%5,%6,%7}, {%8,%9}, {%0,%1,%2,%3};"
        : "+f"(d[0]), "+f"(d[1]), "+f"(d[2]), "+f"(d[3])
        : "r"(a[0]), "r"(a[1]), "r"(a[2]), "r"(a[3]), "r"(b0), "r"(b1));
}

// ============================================================================
// tf32 warp-MMA GEMM:  C[m,n] = sum_k A[m,k] * W[n,k]   (NT, K = D_ = 2048)
// CTA tile 128x128, K-chunk 32, 8 warps of 64x32, double-buffered smem.
// ============================================================================
#define KCH   32
#define SSTR  36
#define STAGE_FLOATS (128 * SSTR)              // 4608
#define GEMM_SMEM_BYTES (4 * STAGE_FLOATS * 4) // 73728 B

__global__ __launch_bounds__(256, 1) void gemm_mma_kernel(
    const float* __restrict__ A, const float* __restrict__ W,
    float* __restrict__ C) {
    extern __shared__ float smg[];
    float* Asm[2] = { smg,                  smg + STAGE_FLOATS };
    float* Bsm[2] = { smg + 2*STAGE_FLOATS, smg + 3*STAGE_FLOATS };

    const int tid  = threadIdx.x;
    const int wid  = tid >> 5;
    const int lane = tid & 31;
    const int lr   = lane >> 2;
    const int lc   = lane & 3;
    const int wm   = wid & 1;
    const int wn   = wid >> 1;
    const int mBase = blockIdx.y << 7;
    const int nBase = blockIdx.x << 7;

    const int grow = tid >> 3;
    const int gc4  = tid & 7;
    const float* Ag = A + (size_t)(mBase + grow) * D_ + gc4 * 4;
    const float* Wg = W + (size_t)(nBase + grow) * D_ + gc4 * 4;

    float4 ra[4], rb[4];
#define GLOAD(k0)                                                        \
    {                                                                    \
        _Pragma("unroll")                                                \
        for (int p = 0; p < 4; ++p) {                                    \
            ra[p] = *(const float4*)(Ag + (size_t)(p*32) * D_ + (k0));   \
            rb[p] = *(const float4*)(Wg + (size_t)(p*32) * D_ + (k0));   \
        }                                                                \
    }
#define SSTORE(buf)                                                      \
    {                                                                    \
        _Pragma("unroll")                                                \
        for (int p = 0; p < 4; ++p) {                                    \
            float* da = &Asm[buf][(grow + p*32) * SSTR + gc4 * 4];       \
            da[0] = __uint_as_float(f2tf(ra[p].x));                      \
            da[1] = __uint_as_float(f2tf(ra[p].y));                      \
            da[2] = __uint_as_float(f2tf(ra[p].z));                      \
            da[3] = __uint_as_float(f2tf(ra[p].w));                      \
            float* db = &Bsm[buf][(grow + p*32) * SSTR + gc4 * 4];       \
            db[0] = __uint_as_float(f2tf(rb[p].x));                      \
            db[1] = __uint_as_float(f2tf(rb[p].y));                      \
            db[2] = __uint_as_float(f2tf(rb[p].z));                      \
            db[3] = __uint_as_float(f2tf(rb[p].w));                      \
        }                                                                \
    }

    float acc[4][4][4];
#pragma unroll
    for (int mf = 0; mf < 4; ++mf)
#pragma unroll
        for (int nf = 0; nf < 4; ++nf)
#pragma unroll
            for (int q = 0; q < 4; ++q) acc[mf][nf][q] = 0.0f;

    const int NS = D_ / KCH;

    GLOAD(0);
    SSTORE(0);
    GLOAD(KCH);
    __syncthreads();

    for (int s = 0; s < NS; ++s) {
        const int b = s & 1;
        const float* As = Asm[b];
        const float* Bs = Bsm[b];

#pragma unroll
        for (int ks = 0; ks < 4; ++ks) {
            const int k0 = ks * 8;
            uint32_t af[4][4];
#pragma unroll
            for (int mf = 0; mf < 4; ++mf) {
                const float* ap = &As[(wm*64 + mf*16 + lr) * SSTR + k0 + lc];
                af[mf][0] = __float_as_uint(ap[0]);
                af[mf][1] = __float_as_uint(ap[8 * SSTR]);
                af[mf][2] = __float_as_uint(ap[4]);
                af[mf][3] = __float_as_uint(ap[8 * SSTR + 4]);
            }
            uint32_t bf[4][2];
#pragma unroll
            for (int nf = 0; nf < 4; ++nf) {
                const float* bp = &Bs[(wn*32 + nf*8 + lr) * SSTR + k0 + lc];
                bf[nf][0] = __float_as_uint(bp[0]);
                bf[nf][1] = __float_as_uint(bp[4]);
            }
#pragma unroll
            for (int mf = 0; mf < 4; ++mf)
#pragma unroll
                for (int nf = 0; nf < 4; ++nf)
                    mma1688(acc[mf][nf], af[mf], bf[nf][0], bf[nf][1]);
        }

        if (s + 1 < NS) {
            SSTORE(1 - b);
            if (s + 2 < NS) GLOAD((s + 2) * KCH);
        }
        __syncthreads();
    }

#pragma unroll
    for (int mf = 0; mf < 4; ++mf) {
#pragma unroll
        for (int nf = 0; nf < 4; ++nf) {
            const int row = mBase + wm*64 + mf*16 + lr;
            const int col = nBase + wn*32 + nf*8 + 2*lc;
            *(float2*)&C[(size_t)row * D_ + col] =
                make_float2(acc[mf][nf][0], acc[mf][nf][1]);
            *(float2*)&C[(size_t)(row + 8) * D_ + col] =
                make_float2(acc[mf][nf][2], acc[mf][nf][3]);
        }
    }
#undef GLOAD
#undef SSTORE
}

// ---------------------------------------------------------------------------
// RoPE applied in-place to Q and K.
// ---------------------------------------------------------------------------
__global__ void rope_kernel(float* __restrict__ Q, float* __restrict__ Kt,
                            const float* __restrict__ cosF,
                            const float* __restrict__ sinF) {
    int idx = blockIdx.x * blockDim.x + threadIdx.x;
    if (idx >= B_ * S_ * H_ * (HD_ / 2)) return;
    int i = idx & 63;
    int h = (idx >> 6) & (H_ - 1);
    int s = (idx >> 10) & (S_ - 1);
    int b = idx >> 21;
    size_t base = ((size_t)(b * S_ + s)) * D_ + h * HD_ + 2 * i;
    float c  = cosF[s * 64 + i];
    float sn = sinF[s * 64 + i];
    float qr = Q[base], qi = Q[base + 1];
    Q[base]     = qr * c - qi * sn;
    Q[base + 1] = qr * sn + qi * c;
    float kr = Kt[base], ki = Kt[base + 1];
    Kt[base]     = kr * c - ki * sn;
    Kt[base + 1] = kr * sn + ki * c;
}

// ============================================================================
// tf32 mma flash attention.
// CTA: 128 q-rows of one (b,h). 8 warps x 16 q-rows. Key tiles of 64.
// Q fragments persistent in registers. K smem stride 132, V stride 136
// (conflict-free row-major and transposed fragment access respectively),
// P staged per-warp in smem (stride 68).
// ============================================================================
#define FK_STR 132
#define FV_STR 136
#define FP_STR 68
#define FKS_OFF 0
#define FVS_OFF (64 * FK_STR)                       // 8448
#define FPS_OFF (FVS_OFF + 64 * FV_STR)             // 17152
#define FLASH_SMEM_FLOATS (FPS_OFF + 8 * 16 * FP_STR)
#define FLASH_SMEM_BYTES  (FLASH_SMEM_FLOATS * 4)   // 103,424 B

__global__ __launch_bounds__(256, 1) void flash_mma_kernel(
    const float* __restrict__ Q, const float* __restrict__ Kg,
    const float* __restrict__ Vg, float* __restrict__ Og) {
    extern __shared__ float smf[];
    float* Ks = smf + FKS_OFF;
    float* Vs = smf + FVS_OFF;
    float* Ps = smf + FPS_OFF;

    const int qi  = blockIdx.x;          // q-tile of 128
    const int h   = blockIdx.y;
    const int b   = blockIdx.z;
    const int tid = threadIdx.x;
    const int wid = tid >> 5;
    const int lane = tid & 31;
    const int lr  = lane >> 2;
    const int lc  = lane & 3;
    const float scale = 0.08838834764831845f;   // 1/sqrt(128)

    const size_t bh = ((size_t)b * S_) * D_ + (size_t)h * HD_;
    const int q0 = qi * 128;
    float* Psw = Ps + wid * 16 * FP_STR;

    // Q fragments: 16 k-steps x 4, persistent in registers.
    uint32_t qa[16][4];
    {
        const float* Qw = Q + bh + (size_t)(q0 + wid * 16) * D_;
#pragma unroll
        for (int ks = 0; ks < 16; ++ks) {
            qa[ks][0] = f2tf(Qw[(size_t)lr * D_ + ks * 8 + lc]);
            qa[ks][1] = f2tf(Qw[(size_t)(lr + 8) * D_ + ks * 8 + lc]);
            qa[ks][2] = f2tf(Qw[(size_t)lr * D_ + ks * 8 + lc + 4]);
            qa[ks][3] = f2tf(Qw[(size_t)(lr + 8) * D_ + ks * 8 + lc + 4]);
        }
    }

    float o[16][4];
#pragma unroll
    for (int nf = 0; nf < 16; ++nf)
#pragma unroll
        for (int q = 0; q < 4; ++q) o[nf][q] = 0.0f;
    float m0 = -1e30f, m1 = -1e30f, l0 = 0.0f, l1 = 0.0f;

    const int r0 = q0 + wid * 16 + lr;
    const int r1 = r0 + 8;
    const int nkt = 2 * qi + 2;

    for (int kt = 0; kt < nkt; ++kt) {
        __syncthreads();
        // Load K,V tile (64x128) -> smem, tf32-rounded.
        {
            const float* kg = Kg + bh + (size_t)(kt * 64) * D_;
            const float* vg = Vg + bh + (size_t)(kt * 64) * D_;
#pragma unroll
            for (int it = 0; it < 8; ++it) {
                int idx = it * 256 + tid;
                int row = idx >> 5;
                int c4  = (idx & 31) << 2;
                float4 kv = *(const float4*)&kg[(size_t)row * D_ + c4];
                float4 vv = *(const float4*)&vg[(size_t)row * D_ + c4];
                float* kd = &Ks[row * FK_STR + c4];
                kd[0] = __uint_as_float(f2tf(kv.x));
                kd[1] = __uint_as_float(f2tf(kv.y));
                kd[2] = __uint_as_float(f2tf(kv.z));
                kd[3] = __uint_as_float(f2tf(kv.w));
                float* vd = &Vs[row * FV_STR + c4];
                vd[0] = __uint_as_float(f2tf(vv.x));
                vd[1] = __uint_as_float(f2tf(vv.y));
                vd[2] = __uint_as_float(f2tf(vv.z));
                vd[3] = __uint_as_float(f2tf(vv.w));
            }
        }
        __syncthreads();

        // QK^T: 8 n-frags (64 keys) x 16 k-steps
        float sc[8][4];
#pragma unroll
        for (int nf = 0; nf < 8; ++nf)
#pragma unroll
            for (int q = 0; q < 4; ++q) sc[nf][q] = 0.0f;
#pragma unroll
        for (int ks = 0; ks < 16; ++ks) {
            uint32_t bf0[8], bf1[8];
#pragma unroll
            for (int nf = 0; nf < 8; ++nf) {
                const float* bp = &Ks[(nf * 8 + lr) * FK_STR + ks * 8 + lc];
                bf0[nf] = __float_as_uint(bp[0]);
                bf1[nf] = __float_as_uint(bp[4]);
            }
#pragma unroll
            for (int nf = 0; nf < 8; ++nf)
                mma1688(sc[nf], qa[ks], bf0[nf], bf1[nf]);
        }

        // scale + mask + online softmax
        const bool needMask = (kt * 64 + 63) > q0;
        float ml0 = -1e30f, ml1 = -1e30f;
#pragma unroll
        for (int nf = 0; nf < 8; ++nf) {
            int c = kt * 64 + nf * 8 + 2 * lc;
            float v0 = sc[nf][0] * scale, v1 = sc[nf][1] * scale;
            float v2 = sc[nf][2] * scale, v3 = sc[nf][3] * scale;
            if (needMask) {
                if (c     > r0) v0 = -1e30f;
                if (c + 1 > r0) v1 = -1e30f;
                if (c     > r1) v2 = -1e30f;
                if (c + 1 > r1) v3 = -1e30f;
            }
            sc[nf][0] = v0; sc[nf][1] = v1; sc[nf][2] = v2; sc[nf][3] = v3;
            ml0 = fmaxf(ml0, fmaxf(v0, v1));
            ml1 = fmaxf(ml1, fmaxf(v2, v3));
        }
        ml0 = fmaxf(ml0, __shfl_xor_sync(0xffffffffu, ml0, 1));
        ml0 = fmaxf(ml0, __shfl_xor_sync(0xffffffffu, ml0, 2));
        ml1 = fmaxf(ml1, __shfl_xor_sync(0xffffffffu, ml1, 1));
        ml1 = fmaxf(ml1, __shfl_xor_sync(0xffffffffu, ml1, 2));

        float mn0 = fmaxf(m0, ml0), mn1 = fmaxf(m1, ml1);
        float a0 = __expf(m0 - mn0), a1 = __expf(m1 - mn1);
        m0 = mn0; m1 = mn1;

        float ps0 = 0.0f, ps1 = 0.0f;
#pragma unroll
        for (int nf = 0; nf < 8; ++nf) {
            float p0 = __expf(sc[nf][0] - mn0);
            float p1 = __expf(sc[nf][1] - mn0);
            float p2 = __expf(sc[nf][2] - mn1);
            float p3 = __expf(sc[nf][3] - mn1);
            ps0 += p0 + p1;
            ps1 += p2 + p3;
            float* pw0 = &Psw[lr * FP_STR + nf * 8 + 2 * lc];
            *(float2*)pw0 = make_float2(__uint_as_float(f2tf(p0)),
                                        __uint_as_float(f2tf(p1)));
            float* pw1 = &Psw[(lr + 8) * FP_STR + nf * 8 + 2 * lc];
            *(float2*)pw1 = make_float2(__uint_as_float(f2tf(p2)),
                                        __uint_as_float(f2tf(p3)));
        }
        ps0 += __shfl_xor_sync(0xffffffffu, ps0, 1);
        ps0 += __shfl_xor_sync(0xffffffffu, ps0, 2);
        ps1 += __shfl_xor_sync(0xffffffffu, ps1, 1);
        ps1 += __shfl_xor_sync(0xffffffffu, ps1, 2);
        l0 = l0 * a0 + ps0;
        l1 = l1 * a1 + ps1;

#pragma unroll
        for (int nf = 0; nf < 16; ++nf) {
            o[nf][0] *= a0; o[nf][1] *= a0;
            o[nf][2] *= a1; o[nf][3] *= a1;
        }
        __syncwarp();

        // PV: o[16 nf over HD=128] += P(16x64) * V(64x128)
#pragma unroll
        for (int ks = 0; ks < 8; ++ks) {
            uint32_t af[4];
            const float* ap = &Psw[lr * FP_STR + ks * 8 + lc];
            af[0] = __float_as_uint(ap[0]);
            af[1] = __float_as_uint(ap[8 * FP_STR]);
            af[2] = __float_as_uint(ap[4]);
            af[3] = __float_as_uint(ap[8 * FP_STR + 4]);
#pragma unroll
            for (int nf = 0; nf < 16; ++nf) {
                const float* bp = &Vs[(ks * 8 + lc) * FV_STR + nf * 8 + lr];
                uint32_t b0 = __float_as_uint(bp[0]);
                uint32_t b1 = __float_as_uint(bp[4 * FV_STR]);
                mma1688(o[nf], af, b0, b1);
            }
        }
    }

    // Epilogue
    float inv0 = 1.0f / l0, inv1 = 1.0f / l1;
    float* Or0 = Og + bh + (size_t)r0 * D_;
    float* Or1 = Og + bh + (size_t)r1 * D_;
#pragma unroll
    for (int nf = 0; nf < 16; ++nf) {
        int c = nf * 8 + 2 * lc;
        *(float2*)&Or0[c] = make_float2(o[nf][0] * inv0, o[nf][1] * inv0);
        *(float2*)&Or1[c] = make_float2(o[nf][2] * inv1, o[nf][3] * inv1);
    }
}

// ---------------------------------------------------------------------------
extern "C" void kernel_launch(void* const* d_in, const int* in_sizes, int n_in,
                              void* d_out, int out_size) {
    const float* x  = (const float*)d_in[0];
    const float* wq = (const float*)d_in[1];
    const float* wk = (const float*)d_in[2];
    const float* wv = (const float*)d_in[3];
    const float* wo = (const float*)d_in[4];
    const float* fc = (const float*)d_in[5];
    const float* fs = (const float*)d_in[6];
    float* out = (float*)d_out;

    void *pq, *pk, *pv, *pa;
    cudaGetSymbolAddress(&pq, g_q);
    cudaGetSymbolAddress(&pk, g_k);
    cudaGetSymbolAddress(&pv, g_v);
    cudaGetSymbolAddress(&pa, g_a);

    cudaFuncSetAttribute(flash_mma_kernel,
                         cudaFuncAttributeMaxDynamicSharedMemorySize, FLASH_SMEM_BYTES);
    cudaFuncSetAttribute(gemm_mma_kernel,
                         cudaFuncAttributeMaxDynamicSharedMemorySize, GEMM_SMEM_BYTES);

    dim3 gemmGrid(D_ / 128, M_ / 128);   // (16, 32)

    gemm_mma_kernel<<<gemmGrid, 256, GEMM_SMEM_BYTES>>>(x, wq, (float*)pq);
    gemm_mma_kernel<<<gemmGrid, 256, GEMM_SMEM_BYTES>>>(x, wk, (float*)pk);
    gemm_mma_kernel<<<gemmGrid, 256, GEMM_SMEM_BYTES>>>(x, wv, (float*)pv);

    int ropeN = B_ * S_ * H_ * (HD_ / 2);
    rope_kernel<<<(ropeN + 255) / 256, 256>>>((float*)pq, (float*)pk, fc, fs);

    flash_mma_kernel<<<dim3(S_ / 128, H_, B_), 256, FLASH_SMEM_BYTES>>>(
        (const float*)pq, (const float*)pk, (const float*)pv, (float*)pa);

    gemm_mma_kernel<<<gemmGrid, 256, GEMM_SMEM_BYTES>>>((const float*)pa, wo, out);
}

// round 5
// speedup vs baseline: 5.3293x; 2.2518x over previous
#include <cuda_runtime.h>
#include <cuda_bf16.h>
#include <cuda_fp16.h>
#include <math.h>
#include <stdint.h>

// Problem constants
#define B_  2
#define S_  2048
#define D_  2048
#define H_  16
#define HD_ 128
#define M_  (B_*S_)

// Scratch (allocation-free rule: __device__ globals)
__device__ float g_q[M_*D_];
__device__ float g_k[M_*D_];
__device__ float g_v[M_*D_];
__device__ float g_a[M_*D_];

// ---------------------------------------------------------------------------
// helpers
// ---------------------------------------------------------------------------
__device__ __forceinline__ uint32_t smem_u32(const void* p) {
    uint32_t a;
    asm("{ .reg .u64 t; cvta.to.shared.u64 t, %1; cvt.u32.u64 %0, t; }"
        : "=r"(a) : "l"(p));
    return a;
}
__device__ __forceinline__ uint32_t packh2(float lo, float hi) {
    __half2 h = __floats2half2_rn(lo, hi);
    return *reinterpret_cast<uint32_t*>(&h);
}
__device__ __forceinline__ void ldsm_x4(uint32_t& r0, uint32_t& r1,
                                        uint32_t& r2, uint32_t& r3, uint32_t a) {
    asm volatile("ldmatrix.sync.aligned.m8n8.x4.shared.b16 {%0,%1,%2,%3}, [%4];"
                 : "=r"(r0), "=r"(r1), "=r"(r2), "=r"(r3) : "r"(a));
}
__device__ __forceinline__ void ldsm_x4t(uint32_t& r0, uint32_t& r1,
                                         uint32_t& r2, uint32_t& r3, uint32_t a) {
    asm volatile("ldmatrix.sync.aligned.m8n8.x4.trans.shared.b16 {%0,%1,%2,%3}, [%4];"
                 : "=r"(r0), "=r"(r1), "=r"(r2), "=r"(r3) : "r"(a));
}
// fp16 mma m16n8k16, f32 accumulate (baseline PTX, sm_80+)
__device__ __forceinline__ void mma16816(float* d, const uint32_t* a,
                                         uint32_t b0, uint32_t b1) {
    asm volatile(
        "mma.sync.aligned.m16n8k16.row.col.f32.f16.f16.f32 "
        "{%0,%1,%2,%3}, {%4,%5,%6,%7}, {%8,%9}, {%0,%1,%2,%3};"
        : "+f"(d[0]), "+f"(d[1]), "+f"(d[2]), "+f"(d[3])
        : "r"(a[0]), "r"(a[1]), "r"(a[2]), "r"(a[3]), "r"(b0), "r"(b1));
}

// ============================================================================
// fp16 warp-MMA GEMM: C[m,n] = sum_k A[m,k]*W[n,k]  (NT, K=2048)
// CTA 128x128, K-chunk 32, 8 warps of 64x32. fp16 smem tiles, ldmatrix frags.
// Optional fused RoPE on the output (ropeFlag).
// Row layout in smem: 32 halves = 16 words + 4 pad = 20 words (bank-clean
// for both ldmatrix phases and STS.64 fills).
// ============================================================================
#define KCH   32
#define ROWW  20
#define STG_W (128 * ROWW)                  // 2560 words / tile stage
#define GEMM_SMEM_BYTES (4 * STG_W * 4)     // 40960 B

__global__ __launch_bounds__(256, 1) void gemm_h_kernel(
    const float* __restrict__ A, const float* __restrict__ W,
    float* __restrict__ C,
    const float* __restrict__ cosF, const float* __restrict__ sinF,
    int ropeFlag) {
    extern __shared__ uint32_t smh[];
    const uint32_t sbase = smem_u32(smh);

    const int tid  = threadIdx.x;
    const int wid  = tid >> 5;
    const int lane = tid & 31;
    const int lr   = lane >> 2;
    const int lc   = lane & 3;
    const int wm   = wid & 1;
    const int wn   = wid >> 1;
    const int mBase = blockIdx.y << 7;
    const int nBase = blockIdx.x << 7;

    // global staging: 8 LDG.128 per thread per stage (4 A + 4 B)
    const int grow = tid >> 3;          // 0..31
    const int gc4  = (tid & 7) * 4;     // 0..28
    const float* Ag = A + (size_t)(mBase + grow) * D_ + gc4;
    const float* Wg = W + (size_t)(nBase + grow) * D_ + gc4;

    float4 ra[4], rb[4];
#define GLOAD(k0)                                                        \
    {                                                                    \
        _Pragma("unroll")                                                \
        for (int p = 0; p < 4; ++p) {                                    \
            ra[p] = *(const float4*)(Ag + (size_t)(p*32) * D_ + (k0));   \
            rb[p] = *(const float4*)(Wg + (size_t)(p*32) * D_ + (k0));   \
        }                                                                \
    }
#define SSTORE(buf)                                                          \
    {                                                                        \
        _Pragma("unroll")                                                    \
        for (int p = 0; p < 4; ++p) {                                        \
            int row = grow + p * 32;                                         \
            uint2 wa = make_uint2(packh2(ra[p].x, ra[p].y),                  \
                                  packh2(ra[p].z, ra[p].w));                 \
            *(uint2*)&smh[(buf)*STG_W + row*ROWW + (tid&7)*2] = wa;          \
            uint2 wb = make_uint2(packh2(rb[p].x, rb[p].y),                  \
                                  packh2(rb[p].z, rb[p].w));                 \
            *(uint2*)&smh[(2+(buf))*STG_W + row*ROWW + (tid&7)*2] = wb;      \
        }                                                                    \
    }

    float acc[4][4][4];
#pragma unroll
    for (int mf = 0; mf < 4; ++mf)
#pragma unroll
        for (int nf = 0; nf < 4; ++nf)
#pragma unroll
            for (int q = 0; q < 4; ++q) acc[mf][nf][q] = 0.0f;

    // ldmatrix per-lane base addresses (bytes)
    const int lrow = lane & 15;
    const int lcol = (lane >> 4) * 4;   // +8 halves for k-high tiles
    const uint32_t aAddr = sbase + (uint32_t)(((wm*64 + lrow)*ROWW + lcol) * 4);
    const uint32_t bAddr = sbase + (uint32_t)((2*STG_W + (wn*32 + lrow)*ROWW + lcol) * 4);

    const int NS = D_ / KCH;   // 64

    GLOAD(0);
    SSTORE(0);
    GLOAD(KCH);
    __syncthreads();

    for (int s = 0; s < NS; ++s) {
        const int b = s & 1;
        const uint32_t ab = aAddr + (uint32_t)(b * STG_W * 4);
        const uint32_t bb = bAddr + (uint32_t)(b * STG_W * 4);

#pragma unroll
        for (int ks = 0; ks < 2; ++ks) {
            uint32_t af[4][4], bq[2][4];
#pragma unroll
            for (int mf = 0; mf < 4; ++mf)
                ldsm_x4(af[mf][0], af[mf][1], af[mf][2], af[mf][3],
                        ab + (uint32_t)((mf*16*ROWW + ks*8) * 4));
#pragma unroll
            for (int np = 0; np < 2; ++np)
                ldsm_x4(bq[np][0], bq[np][1], bq[np][2], bq[np][3],
                        bb + (uint32_t)((np*16*ROWW + ks*8) * 4));
#pragma unroll
            for (int mf = 0; mf < 4; ++mf)
#pragma unroll
                for (int nf = 0; nf < 4; ++nf)
                    mma16816(acc[mf][nf], af[mf],
                             bq[nf>>1][nf&1], bq[nf>>1][(nf&1)+2]);
        }

        if (s + 1 < NS) {
            SSTORE(1 - b);
            if (s + 2 < NS) GLOAD((s + 2) * KCH);
        }
        __syncthreads();
    }

    // Epilogue (+ optional fused RoPE: c0/c1 is exactly an (even,odd) pair)
#pragma unroll
    for (int mf = 0; mf < 4; ++mf) {
#pragma unroll
        for (int nf = 0; nf < 4; ++nf) {
            const int row = mBase + wm*64 + mf*16 + lr;
            const int col = nBase + wn*32 + nf*8 + 2*lc;
            float e0 = acc[mf][nf][0], o0 = acc[mf][nf][1];
            float e1 = acc[mf][nf][2], o1 = acc[mf][nf][3];
            if (ropeFlag) {
                const int i = (col & (HD_-1)) >> 1;
                const int s0 = row & (S_-1);
                const int s1 = (row + 8) & (S_-1);
                float c0 = cosF[s0*64 + i], sn0 = sinF[s0*64 + i];
                float c1 = cosF[s1*64 + i], sn1 = sinF[s1*64 + i];
                float t0 = e0 * c0 - o0 * sn0;
                o0 = e0 * sn0 + o0 * c0; e0 = t0;
                float t1 = e1 * c1 - o1 * sn1;
                o1 = e1 * sn1 + o1 * c1; e1 = t1;
            }
            *(float2*)&C[(size_t)row * D_ + col]       = make_float2(e0, o0);
            *(float2*)&C[(size_t)(row + 8) * D_ + col] = make_float2(e1, o1);
        }
    }
#undef GLOAD
#undef SSTORE
}

// ============================================================================
// fp16 mma flash attention. CTA = 128 q-rows of one (b,h); 8 warps x 16 rows.
// Q frags persistent in regs; K,V tiles in smem (stride 68 words, fp16);
// P stays in registers (C-frag of QK^T == A-frag of PV for fp16).
// ============================================================================
#define FKW 68
#define FVOFF_W (64 * FKW)                  // V tile offset (words)
#define FLASH_SMEM_BYTES (2 * 64 * FKW * 4) // 34816 B

__global__ __launch_bounds__(256, 1) void flash_h_kernel(
    const float* __restrict__ Q, const float* __restrict__ Kg,
    const float* __restrict__ Vg, float* __restrict__ Og) {
    extern __shared__ uint32_t smf[];
    const uint32_t sbase = smem_u32(smf);

    const int qi  = gridDim.x - 1 - blockIdx.x;   // heavy tiles first
    const int h   = blockIdx.y;
    const int b   = blockIdx.z;
    const int tid = threadIdx.x;
    const int wid = tid >> 5;
    const int lane = tid & 31;
    const int lr  = lane >> 2;
    const int lc  = lane & 3;
    const float scale = 0.08838834764831845f;   // 1/sqrt(128)

    const size_t bh = ((size_t)b * S_) * D_ + (size_t)h * HD_;
    const int q0 = qi * 128;

    // Q fragments: 8 k-steps (k16) x 4 regs, packed fp16, persistent.
    uint32_t qa[8][4];
    {
        const float* Qw = Q + bh + (size_t)(q0 + wid * 16) * D_;
#pragma unroll
        for (int ks = 0; ks < 8; ++ks) {
            float2 v0 = *(const float2*)&Qw[(size_t)lr * D_ + ks*16 + 2*lc];
            float2 v1 = *(const float2*)&Qw[(size_t)(lr+8) * D_ + ks*16 + 2*lc];
            float2 v2 = *(const float2*)&Qw[(size_t)lr * D_ + ks*16 + 2*lc + 8];
            float2 v3 = *(const float2*)&Qw[(size_t)(lr+8) * D_ + ks*16 + 2*lc + 8];
            qa[ks][0] = packh2(v0.x, v0.y);
            qa[ks][1] = packh2(v1.x, v1.y);
            qa[ks][2] = packh2(v2.x, v2.y);
            qa[ks][3] = packh2(v3.x, v3.y);
        }
    }

    float o[16][4];
#pragma unroll
    for (int nf = 0; nf < 16; ++nf)
#pragma unroll
        for (int q = 0; q < 4; ++q) o[nf][q] = 0.0f;
    float m0 = -1e30f, m1 = -1e30f, l0 = 0.0f, l1 = 0.0f;

    const int r0 = q0 + wid * 16 + lr;
    const int r1 = r0 + 8;
    const int nkt = 2 * qi + 2;

    // ldmatrix lane bases
    const int lrow = lane & 15;
    const int lcol = (lane >> 4) * 4;
    const uint32_t kb = sbase + (uint32_t)((lrow * FKW + lcol) * 4);
    const uint32_t vb = sbase + (uint32_t)((FVOFF_W + lrow * FKW + lcol) * 4);

    for (int kt = 0; kt < nkt; ++kt) {
        __syncthreads();
        // Load K,V tiles (64x128 f32 -> fp16 smem, stride 68 words)
        {
            const float* kg = Kg + bh + (size_t)(kt * 64) * D_;
            const float* vg = Vg + bh + (size_t)(kt * 64) * D_;
#pragma unroll
            for (int it = 0; it < 8; ++it) {
                int idx = it * 256 + tid;
                int row = idx >> 5;
                int c4  = (idx & 31) << 2;
                float4 kv = *(const float4*)&kg[(size_t)row * D_ + c4];
                float4 vv = *(const float4*)&vg[(size_t)row * D_ + c4];
                *(uint2*)&smf[row * FKW + c4/2] =
                    make_uint2(packh2(kv.x, kv.y), packh2(kv.z, kv.w));
                *(uint2*)&smf[FVOFF_W + row * FKW + c4/2] =
                    make_uint2(packh2(vv.x, vv.y), packh2(vv.z, vv.w));
            }
        }
        __syncthreads();

        // QK^T: sc[8 nf over 64 keys]
        float sc[8][4];
#pragma unroll
        for (int nf = 0; nf < 8; ++nf)
#pragma unroll
            for (int q = 0; q < 4; ++q) sc[nf][q] = 0.0f;
#pragma unroll
        for (int ks = 0; ks < 8; ++ks) {
#pragma unroll
            for (int np = 0; np < 4; ++np) {
                uint32_t b0, b1, b2, b3;
                ldsm_x4(b0, b1, b2, b3,
                        kb + (uint32_t)((np*16*FKW + ks*8) * 4));
                mma16816(sc[2*np],   qa[ks], b0, b2);
                mma16816(sc[2*np+1], qa[ks], b1, b3);
            }
        }

        // scale + causal mask + online softmax
        const bool needMask = (kt * 64 + 63) > q0;
        float ml0 = -1e30f, ml1 = -1e30f;
#pragma unroll
        for (int nf = 0; nf < 8; ++nf) {
            int c = kt * 64 + nf * 8 + 2 * lc;
            float v0 = sc[nf][0] * scale, v1 = sc[nf][1] * scale;
            float v2 = sc[nf][2] * scale, v3 = sc[nf][3] * scale;
            if (needMask) {
                if (c     > r0) v0 = -1e30f;
                if (c + 1 > r0) v1 = -1e30f;
                if (c     > r1) v2 = -1e30f;
                if (c + 1 > r1) v3 = -1e30f;
            }
            sc[nf][0] = v0; sc[nf][1] = v1; sc[nf][2] = v2; sc[nf][3] = v3;
            ml0 = fmaxf(ml0, fmaxf(v0, v1));
            ml1 = fmaxf(ml1, fmaxf(v2, v3));
        }
        ml0 = fmaxf(ml0, __shfl_xor_sync(0xffffffffu, ml0, 1));
        ml0 = fmaxf(ml0, __shfl_xor_sync(0xffffffffu, ml0, 2));
        ml1 = fmaxf(ml1, __shfl_xor_sync(0xffffffffu, ml1, 1));
        ml1 = fmaxf(ml1, __shfl_xor_sync(0xffffffffu, ml1, 2));

        float mn0 = fmaxf(m0, ml0), mn1 = fmaxf(m1, ml1);
        float a0 = __expf(m0 - mn0), a1 = __expf(m1 - mn1);
        m0 = mn0; m1 = mn1;

        float ps0 = 0.0f, ps1 = 0.0f;
#pragma unroll
        for (int nf = 0; nf < 8; ++nf) {
            float p0 = __expf(sc[nf][0] - mn0);
            float p1 = __expf(sc[nf][1] - mn0);
            float p2 = __expf(sc[nf][2] - mn1);
            float p3 = __expf(sc[nf][3] - mn1);
            sc[nf][0] = p0; sc[nf][1] = p1; sc[nf][2] = p2; sc[nf][3] = p3;
            ps0 += p0 + p1;
            ps1 += p2 + p3;
        }
        ps0 += __shfl_xor_sync(0xffffffffu, ps0, 1);
        ps0 += __shfl_xor_sync(0xffffffffu, ps0, 2);
        ps1 += __shfl_xor_sync(0xffffffffu, ps1, 1);
        ps1 += __shfl_xor_sync(0xffffffffu, ps1, 2);
        l0 = l0 * a0 + ps0;
        l1 = l1 * a1 + ps1;

        // pack P into fp16 A-fragments (no smem roundtrip)
        uint32_t ap[4][4];
#pragma unroll
        for (int ks = 0; ks < 4; ++ks) {
            ap[ks][0] = packh2(sc[2*ks][0],   sc[2*ks][1]);
            ap[ks][1] = packh2(sc[2*ks][2],   sc[2*ks][3]);
            ap[ks][2] = packh2(sc[2*ks+1][0], sc[2*ks+1][1]);
            ap[ks][3] = packh2(sc[2*ks+1][2], sc[2*ks+1][3]);
        }

#pragma unroll
        for (int nf = 0; nf < 16; ++nf) {
            o[nf][0] *= a0; o[nf][1] *= a0;
            o[nf][2] *= a1; o[nf][3] *= a1;
        }

        // PV: o += P(16x64) * V(64x128); V frags via ldmatrix.x4.trans
#pragma unroll
        for (int ks = 0; ks < 4; ++ks) {
#pragma unroll
            for (int np = 0; np < 8; ++np) {
                uint32_t b0, b1, b2, b3;
                ldsm_x4t(b0, b1, b2, b3,
                         vb + (uint32_t)((ks*16*FKW + np*8) * 4));
                mma16816(o[2*np],   ap[ks], b0, b1);
                mma16816(o[2*np+1], ap[ks], b2, b3);
            }
        }
    }

    // Epilogue
    float inv0 = 1.0f / l0, inv1 = 1.0f / l1;
    float* Or0 = Og + bh + (size_t)r0 * D_;
    float* Or1 = Og + bh + (size_t)r1 * D_;
#pragma unroll
    for (int nf = 0; nf < 16; ++nf) {
        int c = nf * 8 + 2 * lc;
        *(float2*)&Or0[c] = make_float2(o[nf][0] * inv0, o[nf][1] * inv0);
        *(float2*)&Or1[c] = make_float2(o[nf][2] * inv1, o[nf][3] * inv1);
    }
}

// ---------------------------------------------------------------------------
extern "C" void kernel_launch(void* const* d_in, const int* in_sizes, int n_in,
                              void* d_out, int out_size) {
    const float* x  = (const float*)d_in[0];
    const float* wq = (const float*)d_in[1];
    const float* wk = (const float*)d_in[2];
    const float* wv = (const float*)d_in[3];
    const float* wo = (const float*)d_in[4];
    const float* fc = (const float*)d_in[5];
    const float* fs = (const float*)d_in[6];
    float* out = (float*)d_out;

    void *pq, *pk, *pv, *pa;
    cudaGetSymbolAddress(&pq, g_q);
    cudaGetSymbolAddress(&pk, g_k);
    cudaGetSymbolAddress(&pv, g_v);
    cudaGetSymbolAddress(&pa, g_a);

    cudaFuncSetAttribute(gemm_h_kernel,
                         cudaFuncAttributeMaxDynamicSharedMemorySize, GEMM_SMEM_BYTES);
    cudaFuncSetAttribute(flash_h_kernel,
                         cudaFuncAttributeMaxDynamicSharedMemorySize, FLASH_SMEM_BYTES);

    dim3 gemmGrid(D_ / 128, M_ / 128);   // (16, 32)

    gemm_h_kernel<<<gemmGrid, 256, GEMM_SMEM_BYTES>>>(x, wq, (float*)pq, fc, fs, 1);
    gemm_h_kernel<<<gemmGrid, 256, GEMM_SMEM_BYTES>>>(x, wk, (float*)pk, fc, fs, 1);
    gemm_h_kernel<<<gemmGrid, 256, GEMM_SMEM_BYTES>>>(x, wv, (float*)pv, fc, fs, 0);

    flash_h_kernel<<<dim3(S_ / 128, H_, B_), 256, FLASH_SMEM_BYTES>>>(
        (const float*)pq, (const float*)pk, (const float*)pv, (float*)pa);

    gemm_h_kernel<<<gemmGrid, 256, GEMM_SMEM_BYTES>>>((const float*)pa, wo, out, fc, fs, 0);
}

// round 6
// speedup vs baseline: 6.4295x; 1.2064x over previous
#include <cuda_runtime.h>
#include <cuda_bf16.h>
#include <cuda_fp16.h>
#include <math.h>
#include <stdint.h>

// Problem constants
#define B_  2
#define S_  2048
#define D_  2048
#define H_  16
#define HD_ 128
#define M_  (B_*S_)

// fp16 scratch (allocation-free rule: __device__ globals)
__device__ __half h_x[M_*D_];
__device__ __half h_wq[D_*D_];
__device__ __half h_wk[D_*D_];
__device__ __half h_wv[D_*D_];
__device__ __half h_wo[D_*D_];
__device__ __half h_q[M_*D_];
__device__ __half h_k[M_*D_];
__device__ __half h_v[M_*D_];
__device__ __half h_a[M_*D_];

// ---------------------------------------------------------------------------
// helpers
// ---------------------------------------------------------------------------
__device__ __forceinline__ uint32_t smem_u32(const void* p) {
    uint32_t a;
    asm("{ .reg .u64 t; cvta.to.shared.u64 t, %1; cvt.u32.u64 %0, t; }"
        : "=r"(a) : "l"(p));
    return a;
}
__device__ __forceinline__ uint32_t packh2(float lo, float hi) {
    __half2 h = __floats2half2_rn(lo, hi);
    return *reinterpret_cast<uint32_t*>(&h);
}
__device__ __forceinline__ void ldsm_x4(uint32_t& r0, uint32_t& r1,
                                        uint32_t& r2, uint32_t& r3, uint32_t a) {
    asm volatile("ldmatrix.sync.aligned.m8n8.x4.shared.b16 {%0,%1,%2,%3}, [%4];"
                 : "=r"(r0), "=r"(r1), "=r"(r2), "=r"(r3) : "r"(a));
}
__device__ __forceinline__ void ldsm_x4t(uint32_t& r0, uint32_t& r1,
                                         uint32_t& r2, uint32_t& r3, uint32_t a) {
    asm volatile("ldmatrix.sync.aligned.m8n8.x4.trans.shared.b16 {%0,%1,%2,%3}, [%4];"
                 : "=r"(r0), "=r"(r1), "=r"(r2), "=r"(r3) : "r"(a));
}
__device__ __forceinline__ void mma16816(float* d, const uint32_t* a,
                                         uint32_t b0, uint32_t b1) {
    asm volatile(
        "mma.sync.aligned.m16n8k16.row.col.f32.f16.f16.f32 "
        "{%0,%1,%2,%3}, {%4,%5,%6,%7}, {%8,%9}, {%0,%1,%2,%3};"
        : "+f"(d[0]), "+f"(d[1]), "+f"(d[2]), "+f"(d[3])
        : "r"(a[0]), "r"(a[1]), "r"(a[2]), "r"(a[3]), "r"(b0), "r"(b1));
}
__device__ __forceinline__ void cp16(uint32_t dst, const void* src) {
    asm volatile("cp.async.ca.shared.global [%0], [%1], 16;"
                 :: "r"(dst), "l"(src));
}
__device__ __forceinline__ void cp_commit() {
    asm volatile("cp.async.commit_group;" ::: "memory");
}
template<int N> __device__ __forceinline__ void cp_wait() {
    asm volatile("cp.async.wait_group %0;" :: "n"(N) : "memory");
}

// ---------------------------------------------------------------------------
// f32 -> f16 bulk convert (8 elements/thread)
// ---------------------------------------------------------------------------
__global__ __launch_bounds__(256) void f2h_kernel(
    const float* __restrict__ src, __half* __restrict__ dst, int n8) {
    int i = blockIdx.x * blockDim.x + threadIdx.x;
    if (i >= n8) return;
    const float4* s = (const float4*)src + (size_t)i * 2;
    float4 a = s[0], b = s[1];
    uint4 o = make_uint4(packh2(a.x, a.y), packh2(a.z, a.w),
                         packh2(b.x, b.y), packh2(b.z, b.w));
    *((uint4*)dst + i) = o;
}

// ============================================================================
// fp16 GEMM with cp.async 3-stage pipeline: C = A(MxK) * W(NxK)^T, K=2048.
// CTA 128x128, 8 warps of 64x32, K-chunk 32. Smem row = 32 halves + 8 pad
// (80 B, 16B-aligned rows, ldmatrix conflict-free).
// mode: 0 = f32 out, 1 = fp16 out, 2 = fp16 out + fused RoPE.
// ============================================================================
#define KCH   32
#define ROWB  80
#define STG_B (128 * ROWB)                    // 10240 B per tile
#define GEMM_SMEM_BYTES (3 * 2 * STG_B)       // 61440 B

__global__ __launch_bounds__(256, 2) void gemm_h_kernel(
    const __half* __restrict__ A, const __half* __restrict__ W,
    float* __restrict__ Cf, __half* __restrict__ Ch,
    const float* __restrict__ cosF, const float* __restrict__ sinF,
    int mode) {
    extern __shared__ __align__(16) char smg[];
    const uint32_t sbase = smem_u32(smg);

    const int tid  = threadIdx.x;
    const int wid  = tid >> 5;
    const int lane = tid & 31;
    const int lr   = lane >> 2;
    const int lc   = lane & 3;
    const int wm   = wid & 1;
    const int wn   = wid >> 1;
    const int mBase = blockIdx.y << 7;
    const int nBase = blockIdx.x << 7;

    // cp.async mapping: thread t -> row = t>>1, half-col base (t&1)*16
    const int crow = tid >> 1;
    const int ccol = (tid & 1) * 16;           // halves
    const __half* Agp = A + (size_t)(mBase + crow) * D_ + ccol;
    const __half* Wgp = W + (size_t)(nBase + crow) * D_ + ccol;
    const uint32_t sArow = (uint32_t)(crow * ROWB + ccol * 2);

#define ISSUE(k0, st)                                                        \
    {                                                                        \
        uint32_t base = sbase + (uint32_t)((st) * 2 * STG_B);                \
        cp16(base + sArow,          Agp + (k0));                             \
        cp16(base + sArow + 16,     Agp + (k0) + 8);                         \
        cp16(base + STG_B + sArow,      Wgp + (k0));                         \
        cp16(base + STG_B + sArow + 16, Wgp + (k0) + 8);                     \
        cp_commit();                                                         \
    }

    float acc[4][4][4];
#pragma unroll
    for (int mf = 0; mf < 4; ++mf)
#pragma unroll
        for (int nf = 0; nf < 4; ++nf)
#pragma unroll
            for (int q = 0; q < 4; ++q) acc[mf][nf][q] = 0.0f;

    // ldmatrix lane bases (bytes)
    const int lrow = lane & 15;
    const int lhi  = (lane >> 4) * 16;
    const uint32_t aOff = (uint32_t)((wm*64 + lrow) * ROWB + lhi);
    const uint32_t bOff = (uint32_t)(STG_B + (wn*32 + lrow) * ROWB + lhi);

    const int NS = D_ / KCH;   // 64

    ISSUE(0, 0);
    ISSUE(KCH, 1);

    for (int s = 0; s < NS; ++s) {
        if (s + 1 < NS) cp_wait<1>(); else cp_wait<0>();
        __syncthreads();
        const int buf = s - (s/3)*3;
        const uint32_t sb = sbase + (uint32_t)(buf * 2 * STG_B);

        if (s + 2 < NS) ISSUE((s + 2) * KCH, (s + 2) - ((s + 2)/3)*3);

#pragma unroll
        for (int ks = 0; ks < 2; ++ks) {
            uint32_t af[4][4], bq[2][4];
#pragma unroll
            for (int mf = 0; mf < 4; ++mf)
                ldsm_x4(af[mf][0], af[mf][1], af[mf][2], af[mf][3],
                        sb + aOff + (uint32_t)(mf*16*ROWB + ks*32));
#pragma unroll
            for (int np = 0; np < 2; ++np)
                ldsm_x4(bq[np][0], bq[np][1], bq[np][2], bq[np][3],
                        sb + bOff + (uint32_t)(np*16*ROWB + ks*32));
#pragma unroll
            for (int mf = 0; mf < 4; ++mf)
#pragma unroll
                for (int nf = 0; nf < 4; ++nf)
                    mma16816(acc[mf][nf], af[mf],
                             bq[nf>>1][nf&1], bq[nf>>1][(nf&1)+2]);
        }
        __syncthreads();
    }
#undef ISSUE

    // Epilogue
#pragma unroll
    for (int mf = 0; mf < 4; ++mf) {
#pragma unroll
        for (int nf = 0; nf < 4; ++nf) {
            const int row = mBase + wm*64 + mf*16 + lr;
            const int col = nBase + wn*32 + nf*8 + 2*lc;
            float e0 = acc[mf][nf][0], o0 = acc[mf][nf][1];
            float e1 = acc[mf][nf][2], o1 = acc[mf][nf][3];
            if (mode == 2) {
                const int i = (col & (HD_-1)) >> 1;
                const int s0 = row & (S_-1);
                const int s1 = (row + 8) & (S_-1);
                float c0 = cosF[s0*64 + i], sn0 = sinF[s0*64 + i];
                float c1 = cosF[s1*64 + i], sn1 = sinF[s1*64 + i];
                float t0 = e0 * c0 - o0 * sn0;
                o0 = e0 * sn0 + o0 * c0; e0 = t0;
                float t1 = e1 * c1 - o1 * sn1;
                o1 = e1 * sn1 + o1 * c1; e1 = t1;
            }
            if (mode == 0) {
                *(float2*)&Cf[(size_t)row * D_ + col]       = make_float2(e0, o0);
                *(float2*)&Cf[(size_t)(row + 8) * D_ + col] = make_float2(e1, o1);
            } else {
                *(uint32_t*)&Ch[(size_t)row * D_ + col]       = packh2(e0, o0);
                *(uint32_t*)&Ch[(size_t)(row + 8) * D_ + col] = packh2(e1, o1);
            }
        }
    }
}

// ============================================================================
// fp16 flash attention, cp.async 3-buffer K/V pipeline.
// CTA = 128 q-rows of one (b,h); 8 warps x 16 rows; key tiles of 64.
// Smem row = 128 halves + 8 pad = 272 B.
// ============================================================================
#define FROWB 272
#define FTILE_B (64 * FROWB)               // 17408 B (one tensor tile)
#define FSTG_B  (2 * FTILE_B)              // K+V per stage
#define FLASH_SMEM_BYTES (3 * FSTG_B)      // 104448 B

__global__ __launch_bounds__(256, 1) void flash_h_kernel(
    const __half* __restrict__ Qh, const __half* __restrict__ Kh,
    const __half* __restrict__ Vh, __half* __restrict__ Oh) {
    extern __shared__ __align__(16) char smfc[];
    const uint32_t sbase = smem_u32(smfc);

    const int qi  = gridDim.x - 1 - blockIdx.x;   // heavy tiles first
    const int h   = blockIdx.y;
    const int b   = blockIdx.z;
    const int tid = threadIdx.x;
    const int wid = tid >> 5;
    const int lane = tid & 31;
    const int lr  = lane >> 2;
    const int lc  = lane & 3;
    const float scale = 0.08838834764831845f;

    const size_t bh = ((size_t)b * S_) * D_ + (size_t)h * HD_;
    const int q0 = qi * 128;
    const int nkt = 2 * qi + 2;

    // cp.async mapping: thread t -> row t>>2, 32-half chunk (t&3)
    const int frow = tid >> 2;
    const int fcol = (tid & 3) * 32;              // halves
    const __half* Kgp = Kh + bh + (size_t)frow * D_ + fcol;
    const __half* Vgp = Vh + bh + (size_t)frow * D_ + fcol;
    const uint32_t sKrow = (uint32_t)(frow * FROWB + fcol * 2);

#define FISSUE(kt, st)                                                       \
    {                                                                        \
        uint32_t base = sbase + (uint32_t)((st) * FSTG_B);                   \
        size_t g = (size_t)(kt) * 64 * D_;                                   \
        _Pragma("unroll")                                                    \
        for (int j = 0; j < 4; ++j) {                                        \
            cp16(base + sKrow + j*16,           Kgp + g + j*8);              \
            cp16(base + FTILE_B + sKrow + j*16, Vgp + g + j*8);              \
        }                                                                    \
        cp_commit();                                                         \
    }

    // Q fragments persistent in regs (8 k-steps x 4)
    uint32_t qa[8][4];
    {
        const __half* Qw = Qh + bh + (size_t)(q0 + wid * 16) * D_;
#pragma unroll
        for (int ks = 0; ks < 8; ++ks) {
            qa[ks][0] = *(const uint32_t*)&Qw[(size_t)lr * D_ + ks*16 + 2*lc];
            qa[ks][1] = *(const uint32_t*)&Qw[(size_t)(lr+8) * D_ + ks*16 + 2*lc];
            qa[ks][2] = *(const uint32_t*)&Qw[(size_t)lr * D_ + ks*16 + 2*lc + 8];
            qa[ks][3] = *(const uint32_t*)&Qw[(size_t)(lr+8) * D_ + ks*16 + 2*lc + 8];
        }
    }

    float o[16][4];
#pragma unroll
    for (int nf = 0; nf < 16; ++nf)
#pragma unroll
        for (int q = 0; q < 4; ++q) o[nf][q] = 0.0f;
    float m0 = -1e30f, m1 = -1e30f, l0 = 0.0f, l1 = 0.0f;

    const int r0 = q0 + wid * 16 + lr;
    const int r1 = r0 + 8;

    // ldmatrix lane bases
    const int lrow = lane & 15;
    const int lhi  = (lane >> 4) * 16;
    const uint32_t kOff = (uint32_t)(lrow * FROWB + lhi);
    const uint32_t vOff = (uint32_t)(FTILE_B + lrow * FROWB + lhi);

    FISSUE(0, 0);
    FISSUE(1, 1);

    for (int kt = 0; kt < nkt; ++kt) {
        if (kt + 1 < nkt) cp_wait<1>(); else cp_wait<0>();
        __syncthreads();
        const int buf = kt - (kt/3)*3;
        const uint32_t sb = sbase + (uint32_t)(buf * FSTG_B);

        if (kt + 2 < nkt) FISSUE(kt + 2, (kt + 2) - ((kt + 2)/3)*3);

        // QK^T
        float sc[8][4];
#pragma unroll
        for (int nf = 0; nf < 8; ++nf)
#pragma unroll
            for (int q = 0; q < 4; ++q) sc[nf][q] = 0.0f;
#pragma unroll
        for (int ks = 0; ks < 8; ++ks) {
#pragma unroll
            for (int np = 0; np < 4; ++np) {
                uint32_t b0, b1, b2, b3;
                ldsm_x4(b0, b1, b2, b3,
                        sb + kOff + (uint32_t)(np*16*FROWB + ks*32));
                mma16816(sc[2*np],   qa[ks], b0, b2);
                mma16816(sc[2*np+1], qa[ks], b1, b3);
            }
        }

        // scale + mask + online softmax
        const bool needMask = (kt * 64 + 63) > q0;
        float ml0 = -1e30f, ml1 = -1e30f;
#pragma unroll
        for (int nf = 0; nf < 8; ++nf) {
            int c = kt * 64 + nf * 8 + 2 * lc;
            float v0 = sc[nf][0] * scale, v1 = sc[nf][1] * scale;
            float v2 = sc[nf][2] * scale, v3 = sc[nf][3] * scale;
            if (needMask) {
                if (c     > r0) v0 = -1e30f;
                if (c + 1 > r0) v1 = -1e30f;
                if (c     > r1) v2 = -1e30f;
                if (c + 1 > r1) v3 = -1e30f;
            }
            sc[nf][0] = v0; sc[nf][1] = v1; sc[nf][2] = v2; sc[nf][3] = v3;
            ml0 = fmaxf(ml0, fmaxf(v0, v1));
            ml1 = fmaxf(ml1, fmaxf(v2, v3));
        }
        ml0 = fmaxf(ml0, __shfl_xor_sync(0xffffffffu, ml0, 1));
        ml0 = fmaxf(ml0, __shfl_xor_sync(0xffffffffu, ml0, 2));
        ml1 = fmaxf(ml1, __shfl_xor_sync(0xffffffffu, ml1, 1));
        ml1 = fmaxf(ml1, __shfl_xor_sync(0xffffffffu, ml1, 2));

        float mn0 = fmaxf(m0, ml0), mn1 = fmaxf(m1, ml1);
        float a0 = __expf(m0 - mn0), a1 = __expf(m1 - mn1);
        m0 = mn0; m1 = mn1;

        float ps0 = 0.0f, ps1 = 0.0f;
#pragma unroll
        for (int nf = 0; nf < 8; ++nf) {
            float p0 = __expf(sc[nf][0] - mn0);
            float p1 = __expf(sc[nf][1] - mn0);
            float p2 = __expf(sc[nf][2] - mn1);
            float p3 = __expf(sc[nf][3] - mn1);
            sc[nf][0] = p0; sc[nf][1] = p1; sc[nf][2] = p2; sc[nf][3] = p3;
            ps0 += p0 + p1;
            ps1 += p2 + p3;
        }
        ps0 += __shfl_xor_sync(0xffffffffu, ps0, 1);
        ps0 += __shfl_xor_sync(0xffffffffu, ps0, 2);
        ps1 += __shfl_xor_sync(0xffffffffu, ps1, 1);
        ps1 += __shfl_xor_sync(0xffffffffu, ps1, 2);
        l0 = l0 * a0 + ps0;
        l1 = l1 * a1 + ps1;

        // pack P into fp16 A-frags (register-only)
        uint32_t ap[4][4];
#pragma unroll
        for (int ks = 0; ks < 4; ++ks) {
            ap[ks][0] = packh2(sc[2*ks][0],   sc[2*ks][1]);
            ap[ks][1] = packh2(sc[2*ks][2],   sc[2*ks][3]);
            ap[ks][2] = packh2(sc[2*ks+1][0], sc[2*ks+1][1]);
            ap[ks][3] = packh2(sc[2*ks+1][2], sc[2*ks+1][3]);
        }

#pragma unroll
        for (int nf = 0; nf < 16; ++nf) {
            o[nf][0] *= a0; o[nf][1] *= a0;
            o[nf][2] *= a1; o[nf][3] *= a1;
        }

        // PV via ldmatrix.trans
#pragma unroll
        for (int ks = 0; ks < 4; ++ks) {
#pragma unroll
            for (int np = 0; np < 8; ++np) {
                uint32_t b0, b1, b2, b3;
                ldsm_x4t(b0, b1, b2, b3,
                         sb + vOff + (uint32_t)(ks*16*FROWB + np*32));
                mma16816(o[2*np],   ap[ks], b0, b1);
                mma16816(o[2*np+1], ap[ks], b2, b3);
            }
        }
        __syncthreads();
    }
#undef FISSUE

    // Epilogue -> fp16
    float inv0 = 1.0f / l0, inv1 = 1.0f / l1;
    __half* Or0 = Oh + bh + (size_t)r0 * D_;
    __half* Or1 = Oh + bh + (size_t)r1 * D_;
#pragma unroll
    for (int nf = 0; nf < 16; ++nf) {
        int c = nf * 8 + 2 * lc;
        *(uint32_t*)&Or0[c] = packh2(o[nf][0] * inv0, o[nf][1] * inv0);
        *(uint32_t*)&Or1[c] = packh2(o[nf][2] * inv1, o[nf][3] * inv1);
    }
}

// ---------------------------------------------------------------------------
extern "C" void kernel_launch(void* const* d_in, const int* in_sizes, int n_in,
                              void* d_out, int out_size) {
    const float* x  = (const float*)d_in[0];
    const float* wq = (const float*)d_in[1];
    const float* wk = (const float*)d_in[2];
    const float* wv = (const float*)d_in[3];
    const float* wo = (const float*)d_in[4];
    const float* fc = (const float*)d_in[5];
    const float* fs = (const float*)d_in[6];
    float* out = (float*)d_out;

    void *px, *pwq, *pwk, *pwv, *pwo, *pq, *pk, *pv, *pa;
    cudaGetSymbolAddress(&px,  h_x);
    cudaGetSymbolAddress(&pwq, h_wq);
    cudaGetSymbolAddress(&pwk, h_wk);
    cudaGetSymbolAddress(&pwv, h_wv);
    cudaGetSymbolAddress(&pwo, h_wo);
    cudaGetSymbolAddress(&pq,  h_q);
    cudaGetSymbolAddress(&pk,  h_k);
    cudaGetSymbolAddress(&pv,  h_v);
    cudaGetSymbolAddress(&pa,  h_a);

    cudaFuncSetAttribute(gemm_h_kernel,
                         cudaFuncAttributeMaxDynamicSharedMemorySize, GEMM_SMEM_BYTES);
    cudaFuncSetAttribute(flash_h_kernel,
                         cudaFuncAttributeMaxDynamicSharedMemorySize, FLASH_SMEM_BYTES);

    // converts
    const int nX8 = (M_ * D_) / 8;   // 1M
    const int nW8 = (D_ * D_) / 8;   // 512K
    f2h_kernel<<<nX8 / 256, 256>>>(x,  (__half*)px,  nX8);
    f2h_kernel<<<nW8 / 256, 256>>>(wq, (__half*)pwq, nW8);
    f2h_kernel<<<nW8 / 256, 256>>>(wk, (__half*)pwk, nW8);
    f2h_kernel<<<nW8 / 256, 256>>>(wv, (__half*)pwv, nW8);
    f2h_kernel<<<nW8 / 256, 256>>>(wo, (__half*)pwo, nW8);

    dim3 gemmGrid(D_ / 128, M_ / 128);   // (16, 32)

    gemm_h_kernel<<<gemmGrid, 256, GEMM_SMEM_BYTES>>>(
        (const __half*)px, (const __half*)pwq, nullptr, (__half*)pq, fc, fs, 2);
    gemm_h_kernel<<<gemmGrid, 256, GEMM_SMEM_BYTES>>>(
        (const __half*)px, (const __half*)pwk, nullptr, (__half*)pk, fc, fs, 2);
    gemm_h_kernel<<<gemmGrid, 256, GEMM_SMEM_BYTES>>>(
        (const __half*)px, (const __half*)pwv, nullptr, (__half*)pv, fc, fs, 1);

    flash_h_kernel<<<dim3(S_ / 128, H_, B_), 256, FLASH_SMEM_BYTES>>>(
        (const __half*)pq, (const __half*)pk, (const __half*)pv, (__half*)pa);

    gemm_h_kernel<<<gemmGrid, 256, GEMM_SMEM_BYTES>>>(
        (const __half*)pa, (const __half*)pwo, out, nullptr, fc, fs, 0);
}

// round 7
// speedup vs baseline: 7.7565x; 1.2064x over previous
#include <cuda_runtime.h>
#include <cuda_bf16.h>
#include <cuda_fp16.h>
#include <math.h>
#include <stdint.h>

// Problem constants
#define B_  2
#define S_  2048
#define D_  2048
#define H_  16
#define HD_ 128
#define M_  (B_*S_)

// fp16 scratch (allocation-free rule: __device__ globals)
__device__ __half h_x[M_*D_];
__device__ __half h_wq[D_*D_];
__device__ __half h_wk[D_*D_];
__device__ __half h_wv[D_*D_];
__device__ __half h_wo[D_*D_];
__device__ __half h_q[M_*D_];
__device__ __half h_k[M_*D_];
__device__ __half h_v[M_*D_];
__device__ __half h_a[M_*D_];

// ---------------------------------------------------------------------------
// helpers
// ---------------------------------------------------------------------------
__device__ __forceinline__ uint32_t smem_u32(const void* p) {
    uint32_t a;
    asm("{ .reg .u64 t; cvta.to.shared.u64 t, %1; cvt.u32.u64 %0, t; }"
        : "=r"(a) : "l"(p));
    return a;
}
__device__ __forceinline__ uint32_t packh2(float lo, float hi) {
    __half2 h = __floats2half2_rn(lo, hi);
    return *reinterpret_cast<uint32_t*>(&h);
}
__device__ __forceinline__ void ldsm_x4(uint32_t& r0, uint32_t& r1,
                                        uint32_t& r2, uint32_t& r3, uint32_t a) {
    asm volatile("ldmatrix.sync.aligned.m8n8.x4.shared.b16 {%0,%1,%2,%3}, [%4];"
                 : "=r"(r0), "=r"(r1), "=r"(r2), "=r"(r3) : "r"(a));
}
__device__ __forceinline__ void ldsm_x4t(uint32_t& r0, uint32_t& r1,
                                         uint32_t& r2, uint32_t& r3, uint32_t a) {
    asm volatile("ldmatrix.sync.aligned.m8n8.x4.trans.shared.b16 {%0,%1,%2,%3}, [%4];"
                 : "=r"(r0), "=r"(r1), "=r"(r2), "=r"(r3) : "r"(a));
}
__device__ __forceinline__ void mma16816(float* d, const uint32_t* a,
                                         uint32_t b0, uint32_t b1) {
    asm volatile(
        "mma.sync.aligned.m16n8k16.row.col.f32.f16.f16.f32 "
        "{%0,%1,%2,%3}, {%4,%5,%6,%7}, {%8,%9}, {%0,%1,%2,%3};"
        : "+f"(d[0]), "+f"(d[1]), "+f"(d[2]), "+f"(d[3])
        : "r"(a[0]), "r"(a[1]), "r"(a[2]), "r"(a[3]), "r"(b0), "r"(b1));
}
__device__ __forceinline__ void cp16(uint32_t dst, const void* src) {
    asm volatile("cp.async.ca.shared.global [%0], [%1], 16;"
                 :: "r"(dst), "l"(src));
}
__device__ __forceinline__ void cp_commit() {
    asm volatile("cp.async.commit_group;" ::: "memory");
}
template<int N> __device__ __forceinline__ void cp_wait() {
    asm volatile("cp.async.wait_group %0;" :: "n"(N) : "memory");
}

// ---------------------------------------------------------------------------
// f32 -> f16 bulk converts
// ---------------------------------------------------------------------------
__global__ __launch_bounds__(256) void f2h_kernel(
    const float* __restrict__ src, __half* __restrict__ dst, int n8) {
    int i = blockIdx.x * blockDim.x + threadIdx.x;
    if (i >= n8) return;
    const float4* s = (const float4*)src + (size_t)i * 2;
    float4 a = s[0], b = s[1];
    uint4 o = make_uint4(packh2(a.x, a.y), packh2(a.z, a.w),
                         packh2(b.x, b.y), packh2(b.z, b.w));
    *((uint4*)dst + i) = o;
}
__global__ __launch_bounds__(256) void f2h4_kernel(
    const float* s0, const float* s1, const float* s2, const float* s3,
    __half* d0, __half* d1, __half* d2, __half* d3, int n8) {
    int i = blockIdx.x * blockDim.x + threadIdx.x;
    if (i >= n8) return;
    const float* src = (blockIdx.y == 0) ? s0 : (blockIdx.y == 1) ? s1
                     : (blockIdx.y == 2) ? s2 : s3;
    __half* dst = (blockIdx.y == 0) ? d0 : (blockIdx.y == 1) ? d1
                : (blockIdx.y == 2) ? d2 : d3;
    const float4* s = (const float4*)src + (size_t)i * 2;
    float4 a = s[0], b = s[1];
    uint4 o = make_uint4(packh2(a.x, a.y), packh2(a.z, a.w),
                         packh2(b.x, b.y), packh2(b.z, b.w));
    *((uint4*)dst + i) = o;
}

// ============================================================================
// fp16 GEMM, K-chunk 64, 3-stage cp.async, XOR-swizzled smem (no padding).
// CTA 128x128, 8 warps of 64x32. FUSED: gridDim.z=3 selects {Wq,Wk,Wv} with
// fp16 out (+RoPE for z<2); else single W -> f32 out.
// Smem stage: A rows 0-127, B rows 128-255; row = 64 halves = 128 B.
// swizzled 16B-chunk: chunk' = chunk ^ (row & 7).
// ============================================================================
#define GK   64
#define STG_B 32768
#define GEMM_SMEM_BYTES (3 * STG_B)        // 98304

template<bool FUSED>
__global__ __launch_bounds__(256, 2) void gemm_h_kernel(
    const __half* __restrict__ A,
    const __half* __restrict__ W0, const __half* __restrict__ W1,
    const __half* __restrict__ W2,
    __half* __restrict__ C0, __half* __restrict__ C1, __half* __restrict__ C2,
    float* __restrict__ Cf,
    const float* __restrict__ cosF, const float* __restrict__ sinF) {
    extern __shared__ __align__(16) char smg[];
    const uint32_t sbase = smem_u32(smg);

    const int tid  = threadIdx.x;
    const int wid  = tid >> 5;
    const int lane = tid & 31;
    const int lr   = lane >> 2;
    const int lc   = lane & 3;
    const int wm   = wid & 1;
    const int wn   = wid >> 1;
    const int mBase = blockIdx.y << 7;
    const int nBase = blockIdx.x << 7;

    const __half* W;
    __half* Ch = nullptr;
    bool doRope = false;
    if (FUSED) {
        const int z = blockIdx.z;
        W  = (z == 0) ? W0 : (z == 1) ? W1 : W2;
        Ch = (z == 0) ? C0 : (z == 1) ? C1 : C2;
        doRope = (z < 2);
    } else {
        W = W0;
    }

    // cp.async mapping: thread -> rows r0+32j, 16B chunk c8 (swizzled)
    const int r0 = tid >> 3;          // 0..31
    const int c8 = tid & 7;           // 16B chunk
    const uint32_t cswB = (uint32_t)((c8 ^ (r0 & 7)) * 16);
    const __half* Agp = A + (size_t)(mBase + r0) * D_ + c8 * 8;
    const __half* Wgp = W + (size_t)(nBase + r0) * D_ + c8 * 8;

#define ISSUE(s_, st_)                                                       \
    {                                                                        \
        uint32_t base = sbase + (uint32_t)((st_) * STG_B);                   \
        const int k0 = (s_) * GK;                                            \
        _Pragma("unroll")                                                    \
        for (int j = 0; j < 4; ++j) {                                        \
            cp16(base + (uint32_t)((r0 + 32*j) * 128) + cswB,                \
                 Agp + (size_t)(32*j) * D_ + k0);                            \
            cp16(base + 16384u + (uint32_t)((r0 + 32*j) * 128) + cswB,       \
                 Wgp + (size_t)(32*j) * D_ + k0);                            \
        }                                                                    \
        cp_commit();                                                         \
    }

    float acc[4][4][4];
#pragma unroll
    for (int mf = 0; mf < 4; ++mf)
#pragma unroll
        for (int nf = 0; nf < 4; ++nf)
#pragma unroll
            for (int q = 0; q < 4; ++q) acc[mf][nf][q] = 0.0f;

    // ldmatrix lane addressing
    const int lrow = lane & 15;
    const int hi   = lane >> 4;       // 16B column select
    const int rl7  = lrow & 7;

    const int NS = D_ / GK;   // 32

    ISSUE(0, 0);
    ISSUE(1, 1);

    for (int s = 0; s < NS; ++s) {
        if (s + 1 < NS) cp_wait<1>(); else cp_wait<0>();
        __syncthreads();
        if (s + 2 < NS) ISSUE(s + 2, (s + 2) % 3);
        const uint32_t sb = sbase + (uint32_t)((s % 3) * STG_B);

#pragma unroll
        for (int ks = 0; ks < 4; ++ks) {
            const uint32_t koff = (uint32_t)((((ks*2) + hi) ^ rl7) * 16);
            uint32_t af[4][4], bq[2][4];
#pragma unroll
            for (int mf = 0; mf < 4; ++mf)
                ldsm_x4(af[mf][0], af[mf][1], af[mf][2], af[mf][3],
                        sb + (uint32_t)((wm*64 + mf*16 + lrow) * 128) + koff);
#pragma unroll
            for (int np = 0; np < 2; ++np)
                ldsm_x4(bq[np][0], bq[np][1], bq[np][2], bq[np][3],
                        sb + 16384u
                           + (uint32_t)((wn*32 + np*16 + lrow) * 128) + koff);
#pragma unroll
            for (int mf = 0; mf < 4; ++mf)
#pragma unroll
                for (int nf = 0; nf < 4; ++nf)
                    mma16816(acc[mf][nf], af[mf],
                             bq[nf>>1][nf&1], bq[nf>>1][(nf&1)+2]);
        }
    }
#undef ISSUE

    // Epilogue
#pragma unroll
    for (int mf = 0; mf < 4; ++mf) {
#pragma unroll
        for (int nf = 0; nf < 4; ++nf) {
            const int row = mBase + wm*64 + mf*16 + lr;
            const int col = nBase + wn*32 + nf*8 + 2*lc;
            float e0 = acc[mf][nf][0], o0 = acc[mf][nf][1];
            float e1 = acc[mf][nf][2], o1 = acc[mf][nf][3];
            if (FUSED) {
                if (doRope) {
                    const int i = (col & (HD_-1)) >> 1;
                    const int s0 = row & (S_-1);
                    const int s1 = (row + 8) & (S_-1);
                    float c0 = cosF[s0*64 + i], sn0 = sinF[s0*64 + i];
                    float c1 = cosF[s1*64 + i], sn1 = sinF[s1*64 + i];
                    float t0 = e0 * c0 - o0 * sn0;
                    o0 = e0 * sn0 + o0 * c0; e0 = t0;
                    float t1 = e1 * c1 - o1 * sn1;
                    o1 = e1 * sn1 + o1 * c1; e1 = t1;
                }
                *(uint32_t*)&Ch[(size_t)row * D_ + col]       = packh2(e0, o0);
                *(uint32_t*)&Ch[(size_t)(row + 8) * D_ + col] = packh2(e1, o1);
            } else {
                *(float2*)&Cf[(size_t)row * D_ + col]       = make_float2(e0, o0);
                *(float2*)&Cf[(size_t)(row + 8) * D_ + col] = make_float2(e1, o1);
            }
        }
    }
}

// ============================================================================
// fp16 flash attention, cp.async 3-buffer K/V pipeline (unchanged from R6).
// ============================================================================
#define FROWB 272
#define FTILE_B (64 * FROWB)
#define FSTG_B  (2 * FTILE_B)
#define FLASH_SMEM_BYTES (3 * FSTG_B)      // 104448 B

__global__ __launch_bounds__(256, 1) void flash_h_kernel(
    const __half* __restrict__ Qh, const __half* __restrict__ Kh,
    const __half* __restrict__ Vh, __half* __restrict__ Oh) {
    extern __shared__ __align__(16) char smfc[];
    const uint32_t sbase = smem_u32(smfc);

    const int qi  = gridDim.x - 1 - blockIdx.x;
    const int h   = blockIdx.y;
    const int b   = blockIdx.z;
    const int tid = threadIdx.x;
    const int wid = tid >> 5;
    const int lane = tid & 31;
    const int lr  = lane >> 2;
    const int lc  = lane & 3;
    const float scale = 0.08838834764831845f;

    const size_t bh = ((size_t)b * S_) * D_ + (size_t)h * HD_;
    const int q0 = qi * 128;
    const int nkt = 2 * qi + 2;

    const int frow = tid >> 2;
    const int fcol = (tid & 3) * 32;
    const __half* Kgp = Kh + bh + (size_t)frow * D_ + fcol;
    const __half* Vgp = Vh + bh + (size_t)frow * D_ + fcol;
    const uint32_t sKrow = (uint32_t)(frow * FROWB + fcol * 2);

#define FISSUE(kt, st)                                                       \
    {                                                                        \
        uint32_t base = sbase + (uint32_t)((st) * FSTG_B);                   \
        size_t g = (size_t)(kt) * 64 * D_;                                   \
        _Pragma("unroll")                                                    \
        for (int j = 0; j < 4; ++j) {                                        \
            cp16(base + sKrow + j*16,           Kgp + g + j*8);              \
            cp16(base + FTILE_B + sKrow + j*16, Vgp + g + j*8);              \
        }                                                                    \
        cp_commit();                                                         \
    }

    uint32_t qa[8][4];
    {
        const __half* Qw = Qh + bh + (size_t)(q0 + wid * 16) * D_;
#pragma unroll
        for (int ks = 0; ks < 8; ++ks) {
            qa[ks][0] = *(const uint32_t*)&Qw[(size_t)lr * D_ + ks*16 + 2*lc];
            qa[ks][1] = *(const uint32_t*)&Qw[(size_t)(lr+8) * D_ + ks*16 + 2*lc];
            qa[ks][2] = *(const uint32_t*)&Qw[(size_t)lr * D_ + ks*16 + 2*lc + 8];
            qa[ks][3] = *(const uint32_t*)&Qw[(size_t)(lr+8) * D_ + ks*16 + 2*lc + 8];
        }
    }

    float o[16][4];
#pragma unroll
    for (int nf = 0; nf < 16; ++nf)
#pragma unroll
        for (int q = 0; q < 4; ++q) o[nf][q] = 0.0f;
    float m0 = -1e30f, m1 = -1e30f, l0 = 0.0f, l1 = 0.0f;

    const int r0 = q0 + wid * 16 + lr;
    const int r1 = r0 + 8;

    const int lrow = lane & 15;
    const int lhi  = (lane >> 4) * 16;
    const uint32_t kOff = (uint32_t)(lrow * FROWB + lhi);
    const uint32_t vOff = (uint32_t)(FTILE_B + lrow * FROWB + lhi);

    FISSUE(0, 0);
    FISSUE(1, 1);

    for (int kt = 0; kt < nkt; ++kt) {
        if (kt + 1 < nkt) cp_wait<1>(); else cp_wait<0>();
        __syncthreads();
        const int buf = kt - (kt/3)*3;
        const uint32_t sb = sbase + (uint32_t)(buf * FSTG_B);

        if (kt + 2 < nkt) FISSUE(kt + 2, (kt + 2) - ((kt + 2)/3)*3);

        float sc[8][4];
#pragma unroll
        for (int nf = 0; nf < 8; ++nf)
#pragma unroll
            for (int q = 0; q < 4; ++q) sc[nf][q] = 0.0f;
#pragma unroll
        for (int ks = 0; ks < 8; ++ks) {
#pragma unroll
            for (int np = 0; np < 4; ++np) {
                uint32_t b0, b1, b2, b3;
                ldsm_x4(b0, b1, b2, b3,
                        sb + kOff + (uint32_t)(np*16*FROWB + ks*32));
                mma16816(sc[2*np],   qa[ks], b0, b2);
                mma16816(sc[2*np+1], qa[ks], b1, b3);
            }
        }

        const bool needMask = (kt * 64 + 63) > q0;
        float ml0 = -1e30f, ml1 = -1e30f;
#pragma unroll
        for (int nf = 0; nf < 8; ++nf) {
            int c = kt * 64 + nf * 8 + 2 * lc;
            float v0 = sc[nf][0] * scale, v1 = sc[nf][1] * scale;
            float v2 = sc[nf][2] * scale, v3 = sc[nf][3] * scale;
            if (needMask) {
                if (c     > r0) v0 = -1e30f;
                if (c + 1 > r0) v1 = -1e30f;
                if (c     > r1) v2 = -1e30f;
                if (c + 1 > r1) v3 = -1e30f;
            }
            sc[nf][0] = v0; sc[nf][1] = v1; sc[nf][2] = v2; sc[nf][3] = v3;
            ml0 = fmaxf(ml0, fmaxf(v0, v1));
            ml1 = fmaxf(ml1, fmaxf(v2, v3));
        }
        ml0 = fmaxf(ml0, __shfl_xor_sync(0xffffffffu, ml0, 1));
        ml0 = fmaxf(ml0, __shfl_xor_sync(0xffffffffu, ml0, 2));
        ml1 = fmaxf(ml1, __shfl_xor_sync(0xffffffffu, ml1, 1));
        ml1 = fmaxf(ml1, __shfl_xor_sync(0xffffffffu, ml1, 2));

        float mn0 = fmaxf(m0, ml0), mn1 = fmaxf(m1, ml1);
        float a0 = __expf(m0 - mn0), a1 = __expf(m1 - mn1);
        m0 = mn0; m1 = mn1;

        float ps0 = 0.0f, ps1 = 0.0f;
#pragma unroll
        for (int nf = 0; nf < 8; ++nf) {
            float p0 = __expf(sc[nf][0] - mn0);
            float p1 = __expf(sc[nf][1] - mn0);
            float p2 = __expf(sc[nf][2] - mn1);
            float p3 = __expf(sc[nf][3] - mn1);
            sc[nf][0] = p0; sc[nf][1] = p1; sc[nf][2] = p2; sc[nf][3] = p3;
            ps0 += p0 + p1;
            ps1 += p2 + p3;
        }
        ps0 += __shfl_xor_sync(0xffffffffu, ps0, 1);
        ps0 += __shfl_xor_sync(0xffffffffu, ps0, 2);
        ps1 += __shfl_xor_sync(0xffffffffu, ps1, 1);
        ps1 += __shfl_xor_sync(0xffffffffu, ps1, 2);
        l0 = l0 * a0 + ps0;
        l1 = l1 * a1 + ps1;

        uint32_t ap[4][4];
#pragma unroll
        for (int ks = 0; ks < 4; ++ks) {
            ap[ks][0] = packh2(sc[2*ks][0],   sc[2*ks][1]);
            ap[ks][1] = packh2(sc[2*ks][2],   sc[2*ks][3]);
            ap[ks][2] = packh2(sc[2*ks+1][0], sc[2*ks+1][1]);
            ap[ks][3] = packh2(sc[2*ks+1][2], sc[2*ks+1][3]);
        }

#pragma unroll
        for (int nf = 0; nf < 16; ++nf) {
            o[nf][0] *= a0; o[nf][1] *= a0;
            o[nf][2] *= a1; o[nf][3] *= a1;
        }

#pragma unroll
        for (int ks = 0; ks < 4; ++ks) {
#pragma unroll
            for (int np = 0; np < 8; ++np) {
                uint32_t b0, b1, b2, b3;
                ldsm_x4t(b0, b1, b2, b3,
                         sb + vOff + (uint32_t)(ks*16*FROWB + np*32));
                mma16816(o[2*np],   ap[ks], b0, b1);
                mma16816(o[2*np+1], ap[ks], b2, b3);
            }
        }
        __syncthreads();
    }
#undef FISSUE

    float inv0 = 1.0f / l0, inv1 = 1.0f / l1;
    __half* Or0 = Oh + bh + (size_t)r0 * D_;
    __half* Or1 = Oh + bh + (size_t)r1 * D_;
#pragma unroll
    for (int nf = 0; nf < 16; ++nf) {
        int c = nf * 8 + 2 * lc;
        *(uint32_t*)&Or0[c] = packh2(o[nf][0] * inv0, o[nf][1] * inv0);
        *(uint32_t*)&Or1[c] = packh2(o[nf][2] * inv1, o[nf][3] * inv1);
    }
}

// ---------------------------------------------------------------------------
extern "C" void kernel_launch(void* const* d_in, const int* in_sizes, int n_in,
                              void* d_out, int out_size) {
    const float* x  = (const float*)d_in[0];
    const float* wq = (const float*)d_in[1];
    const float* wk = (const float*)d_in[2];
    const float* wv = (const float*)d_in[3];
    const float* wo = (const float*)d_in[4];
    const float* fc = (const float*)d_in[5];
    const float* fs = (const float*)d_in[6];
    float* out = (float*)d_out;

    void *px, *pwq, *pwk, *pwv, *pwo, *pq, *pk, *pv, *pa;
    cudaGetSymbolAddress(&px,  h_x);
    cudaGetSymbolAddress(&pwq, h_wq);
    cudaGetSymbolAddress(&pwk, h_wk);
    cudaGetSymbolAddress(&pwv, h_wv);
    cudaGetSymbolAddress(&pwo, h_wo);
    cudaGetSymbolAddress(&pq,  h_q);
    cudaGetSymbolAddress(&pk,  h_k);
    cudaGetSymbolAddress(&pv,  h_v);
    cudaGetSymbolAddress(&pa,  h_a);

    cudaFuncSetAttribute(gemm_h_kernel<true>,
                         cudaFuncAttributeMaxDynamicSharedMemorySize, GEMM_SMEM_BYTES);
    cudaFuncSetAttribute(gemm_h_kernel<false>,
                         cudaFuncAttributeMaxDynamicSharedMemorySize, GEMM_SMEM_BYTES);
    cudaFuncSetAttribute(flash_h_kernel,
                         cudaFuncAttributeMaxDynamicSharedMemorySize, FLASH_SMEM_BYTES);

    const int nX8 = (M_ * D_) / 8;
    const int nW8 = (D_ * D_) / 8;
    f2h_kernel<<<nX8 / 256, 256>>>(x, (__half*)px, nX8);
    f2h4_kernel<<<dim3(nW8 / 256, 4), 256>>>(
        wq, wk, wv, wo,
        (__half*)pwq, (__half*)pwk, (__half*)pwv, (__half*)pwo, nW8);

    // Fused QKV projections (+RoPE on Q,K)
    gemm_h_kernel<true><<<dim3(D_ / 128, M_ / 128, 3), 256, GEMM_SMEM_BYTES>>>(
        (const __half*)px,
        (const __half*)pwq, (const __half*)pwk, (const __half*)pwv,
        (__half*)pq, (__half*)pk, (__half*)pv, nullptr, fc, fs);

    flash_h_kernel<<<dim3(S_ / 128, H_, B_), 256, FLASH_SMEM_BYTES>>>(
        (const __half*)pq, (const __half*)pk, (const __half*)pv, (__half*)pa);

    // Output projection -> f32
    gemm_h_kernel<false><<<dim3(D_ / 128, M_ / 128, 1), 256, GEMM_SMEM_BYTES>>>(
        (const __half*)pa,
        (const __half*)pwo, nullptr, nullptr,
        nullptr, nullptr, nullptr, out, fc, fs);
}